// round 7
// baseline (speedup 1.0000x reference)
#include <cuda_runtime.h>

#define NB 1024
#define NT 256
#define NS 16
#define NM 4
#define NSTEP 255
#define ROWF 20
#define CH 15            // chunk: 255 = 17 * 15
#define NCHUNK 17
#define CHF4 (CH * 100)  // float4 per chunk = 1500

// blob[t]: 100 float4 per step, float4-column-major:
//   f4 index (c*20 + row): row<16 state rows [A|L], row 16+m = [HA|HB] rows.
//   Column block c<4 covers matrix cols 4c..4c+3; c==4 covers cols 16..19 (L/HB).
__device__ float4 g_blob[NSTEP * 100];
__device__ float  g_s0[16];
__device__ float  g_y0[4];
__device__ int    g_ready;   // chunks published (monotonic within a launch)

__global__ void reset_kernel() { g_ready = 0; }

// ---------------------------------------------------------------------------
// KF consumer step: lanes 0..15 new state, lanes 16..19 write output.
// ---------------------------------------------------------------------------
#define KF_STEP(Ab, ob, tt)                                                    \
    do {                                                                       \
        float acc0, acc1, res;                                                 \
        acc0 = (Ab)[0].x * __shfl_sync(0xffffffffu, x, 0);                     \
        acc1 = (Ab)[0].y * __shfl_sync(0xffffffffu, x, 1);                     \
        acc0 = fmaf((Ab)[0].z, __shfl_sync(0xffffffffu, x, 2), acc0);          \
        acc1 = fmaf((Ab)[0].w, __shfl_sync(0xffffffffu, x, 3), acc1);          \
        acc0 = fmaf((Ab)[1].x, __shfl_sync(0xffffffffu, x, 4), acc0);          \
        acc1 = fmaf((Ab)[1].y, __shfl_sync(0xffffffffu, x, 5), acc1);          \
        acc0 = fmaf((Ab)[1].z, __shfl_sync(0xffffffffu, x, 6), acc0);          \
        acc1 = fmaf((Ab)[1].w, __shfl_sync(0xffffffffu, x, 7), acc1);          \
        acc0 = fmaf((Ab)[2].x, __shfl_sync(0xffffffffu, x, 8), acc0);          \
        acc1 = fmaf((Ab)[2].y, __shfl_sync(0xffffffffu, x, 9), acc1);          \
        acc0 = fmaf((Ab)[2].z, __shfl_sync(0xffffffffu, x, 10), acc0);         \
        acc1 = fmaf((Ab)[2].w, __shfl_sync(0xffffffffu, x, 11), acc1);         \
        acc0 = fmaf((Ab)[3].x, __shfl_sync(0xffffffffu, x, 12), acc0);         \
        acc1 = fmaf((Ab)[3].y, __shfl_sync(0xffffffffu, x, 13), acc1);         \
        acc0 = fmaf((Ab)[3].z, __shfl_sync(0xffffffffu, x, 14), acc0);         \
        acc1 = fmaf((Ab)[3].w, __shfl_sync(0xffffffffu, x, 15), acc1);         \
        acc0 = fmaf((Ab)[4].x, (ob).x, acc0);                                  \
        acc1 = fmaf((Ab)[4].y, (ob).y, acc1);                                  \
        acc0 = fmaf((Ab)[4].z, (ob).z, acc0);                                  \
        acc1 = fmaf((Ab)[4].w, (ob).w, acc1);                                  \
        res = acc0 + acc1;                                                     \
        if (lane < 16) x = res;                                                \
        else if (lane < 20) op[((tt) + 1) * 4 + (lane - 16)] = res;            \
    } while (0)

__global__ __launch_bounds__(256, 1) void fused_kernel(
    const float* __restrict__ inp, float* __restrict__ out,
    const float* __restrict__ F, const float* __restrict__ H,
    const float* __restrict__ Q, const float* __restrict__ R,
    const float* __restrict__ x0, const float* __restrict__ sd)
{
    // producer shared state
    __shared__ float sP[16][ROWF];
    __shared__ float sT[16][ROWF];
    __shared__ float sA[16][ROWF];
    __shared__ float sF[16][ROWF];
    __shared__ float sQ[16][ROWF];
    __shared__ float sH[4][ROWF];
    __shared__ float sHF[4][ROWF];
    __shared__ float sHP[4][ROWF];
    __shared__ float sHA[4][ROWF];
    __shared__ __align__(16) float sFHP[16][4];
    __shared__ __align__(16) float sL[16][4];
    __shared__ __align__(16) float sLR[16][4];
    __shared__ float sS[4][4], sSi[4][4], scof[4][4], sR[4][4], sHB[4][4], sSiR[4][4];
    __shared__ float ssd2[16], ss0[16];
    // consumer staging buffer
    __shared__ __align__(16) float4 sbuf[CHF4];   // 24 KB

    const int tid = threadIdx.x;

    if (blockIdx.x == 0) {
        // ================= PRODUCER: Joseph Riccati, 3 barriers/step ========
        const int i = tid >> 4, j = tid & 15;

        sF[i][j] = F[i * 16 + j];
        sQ[i][j] = Q[i * 16 + j];
        if (i < 4) sH[i][j] = H[i * 16 + j];
        if (tid < 16) {
            sR[tid >> 2][tid & 3] = R[tid];
            float v = sd[tid];
            ssd2[tid] = v * v;
        }
        __syncthreads();

        // P0 = F diag(sd^2) F^T + Q ; s0 = F x0 ; HF = H F (tid 64..127)
        {
            float a0 = sQ[i][j], a1 = 0.f, a2 = 0.f, a3 = 0.f;
#pragma unroll
            for (int k = 0; k < 16; k += 4) {
                a0 = fmaf(sF[i][k + 0] * ssd2[k + 0], sF[j][k + 0], a0);
                a1 = fmaf(sF[i][k + 1] * ssd2[k + 1], sF[j][k + 1], a1);
                a2 = fmaf(sF[i][k + 2] * ssd2[k + 2], sF[j][k + 2], a2);
                a3 = fmaf(sF[i][k + 3] * ssd2[k + 3], sF[j][k + 3], a3);
            }
            sP[i][j] = (a0 + a1) + (a2 + a3);
        }
        if (tid < 16) {
            float acc = 0.f;
#pragma unroll
            for (int k = 0; k < 16; k++) acc = fmaf(sF[tid][k], x0[k], acc);
            ss0[tid] = acc;
            g_s0[tid] = acc;
        }
        if (tid >= 64 && tid < 128) {
            int m = (tid - 64) >> 4, jj = tid & 15;
            float acc = 0.f;
#pragma unroll
            for (int k = 0; k < 16; k++) acc = fmaf(sH[m][k], sF[k][jj], acc);
            sHF[m][jj] = acc;
        }
        // warp0 register preloads (reads sH/sF, valid after first sync)
        const int mA = tid >> 4, jA = tid & 15;       // HP/HA mapping (tid<32)
        const int iF = tid >> 2, nF = tid & 3;        // FHP/L/LR mapping
        const int mS = tid >> 2, nS = tid & 3;        // lanes 0..15
        const int iA = tid >> 1, jb = (tid & 1) << 3; // A mapping
        float hR0[16], hR2[16], fR0[16], fR8[16];
        if (tid < 32) {
#pragma unroll
            for (int k = 0; k < 16; k++) {
                hR0[k] = sH[mA][k];
                hR2[k] = sH[mA + 2][k];
                fR0[k] = sF[iF][k];
                fR8[k] = sF[iF + 8][k];
            }
        }
        __syncthreads();
        if (tid < 4) {
            float acc = 0.f;
#pragma unroll
            for (int k = 0; k < 16; k++) acc = fmaf(sH[tid][k], ss0[k], acc);
            g_y0[tid] = acc;
        }

        float* blob = (float*)g_blob;

#pragma unroll 1
        for (int t = 0; t < NSTEP; ++t) {
            // ============ warp0: full measurement-side chain ============
            if (tid < 32) {
                // HP[m][j] = sum_k H[m][k] P[k][j]   (2 elements per lane)
                float hp0 = 0.f, hp1 = 0.f, hp2 = 0.f, hp3 = 0.f;
#pragma unroll
                for (int k = 0; k < 16; k += 2) {
                    float pa = sP[k][jA], pb = sP[k + 1][jA];
                    hp0 = fmaf(hR0[k], pa, hp0);
                    hp1 = fmaf(hR0[k + 1], pb, hp1);
                    hp2 = fmaf(hR2[k], pa, hp2);
                    hp3 = fmaf(hR2[k + 1], pb, hp3);
                }
                sHP[mA][jA] = hp0 + hp1;
                sHP[mA + 2][jA] = hp2 + hp3;
                __syncwarp();
                // S = HP H^T + R  (lanes 0..15)
                if (tid < 16) {
                    float s0 = sR[mS][nS], s1 = 0.f;
#pragma unroll
                    for (int k = 0; k < 16; k += 2) {
                        s0 = fmaf(sHP[mS][k], sH[nS][k], s0);
                        s1 = fmaf(sHP[mS][k + 1], sH[nS][k + 1], s1);
                    }
                    sS[mS][nS] = s0 + s1;
                }
                __syncwarp();
                // cofactors (lanes 0..15)
                if (tid < 16) {
                    int r0 = 0 + (0 >= mS), r1 = 1 + (1 >= mS), r2 = 2 + (2 >= mS);
                    int c0 = 0 + (0 >= nS), c1 = 1 + (1 >= nS), c2 = 2 + (2 >= nS);
                    float a = sS[r0][c0], b = sS[r0][c1], c = sS[r0][c2];
                    float d = sS[r1][c0], e = sS[r1][c1], f = sS[r1][c2];
                    float g = sS[r2][c0], h = sS[r2][c1], i2 = sS[r2][c2];
                    float minor = a * (e * i2 - f * h) - b * (d * i2 - f * g) + c * (d * h - e * g);
                    scof[mS][nS] = ((mS + nS) & 1) ? -minor : minor;
                }
                __syncwarp();
                float rdet = 0.f;
                if (tid == 0) {
                    float det = sS[0][0] * scof[0][0] + sS[0][1] * scof[0][1] +
                                sS[0][2] * scof[0][2] + sS[0][3] * scof[0][3];
                    rdet = __fdividef(1.f, det);
                }
                rdet = __shfl_sync(0xffffffffu, rdet, 0);
                // Si = adj(S)/det ; SiR = Si R  (from cofactors, same region)
                if (tid < 16) {
                    sSi[mS][nS] = scof[nS][mS] * rdet;
                    float sr0 = 0.f, sr1 = 0.f;
#pragma unroll
                    for (int p = 0; p < 4; p += 2) {
                        sr0 = fmaf(scof[p][mS], sR[p][nS], sr0);
                        sr1 = fmaf(scof[p + 1][mS], sR[p + 1][nS], sr1);
                    }
                    sSiR[mS][nS] = (sr0 + sr1) * rdet;
                }
                __syncwarp();
                // FHP[i][n] = sum_k F[i][k] HP[n][k]  (2 elements per lane)
                float f0 = 0.f, f1 = 0.f, f2 = 0.f, f3 = 0.f;
#pragma unroll
                for (int k = 0; k < 16; k += 2) {
                    float ha = sHP[nF][k], hb = sHP[nF][k + 1];
                    f0 = fmaf(fR0[k], ha, f0);
                    f1 = fmaf(fR0[k + 1], hb, f1);
                    f2 = fmaf(fR8[k], ha, f2);
                    f3 = fmaf(fR8[k + 1], hb, f3);
                }
                sFHP[iF][nF] = f0 + f1;
                sFHP[iF + 8][nF] = f2 + f3;
                __syncwarp();
                // L = FHP Si ; LR = FHP SiR  (2 elements per lane each)
                float L0 = 0.f, L1 = 0.f, q0 = 0.f, q1 = 0.f;
#pragma unroll
                for (int n = 0; n < 4; n++) {
                    float a0 = sFHP[iF][n], a1 = sFHP[iF + 8][n];
                    float si = sSi[n][nF], sr = sSiR[n][nF];
                    L0 = fmaf(a0, si, L0);
                    L1 = fmaf(a1, si, L1);
                    q0 = fmaf(a0, sr, q0);
                    q1 = fmaf(a1, sr, q1);
                }
                sL[iF][nF] = L0;
                sL[iF + 8][nF] = L1;
                sLR[iF][nF] = q0;
                sLR[iF + 8][nF] = q1;
                __syncwarp();
                // A = F - L H  (8 columns per lane)  ;  HB = H L (lanes 0..15)
                {
                    float l0 = sL[iA][0], l1 = sL[iA][1], l2 = sL[iA][2], l3 = sL[iA][3];
#pragma unroll
                    for (int q = 0; q < 8; q++) {
                        int j2 = jb + q;
                        float a = sF[iA][j2];
                        a = fmaf(-l0, sH[0][j2], a);
                        a = fmaf(-l1, sH[1][j2], a);
                        a = fmaf(-l2, sH[2][j2], a);
                        a = fmaf(-l3, sH[3][j2], a);
                        sA[iA][j2] = a;
                    }
                }
                if (tid < 16) {
                    float hb0 = 0.f, hb1 = 0.f;
#pragma unroll
                    for (int k = 0; k < 16; k += 2) {
                        hb0 = fmaf(sH[mS][k], sL[k][nS], hb0);
                        hb1 = fmaf(sH[mS][k + 1], sL[k + 1][nS], hb1);
                    }
                    sHB[mS][nS] = hb0 + hb1;
                }
                __syncwarp();
                // HA = HF - HB H  (2 elements per lane)
                {
                    float ha0 = sHF[mA][jA], ha1 = sHF[mA + 2][jA];
#pragma unroll
                    for (int n = 0; n < 4; n++) {
                        float hn = sH[n][jA];
                        ha0 = fmaf(-sHB[mA][n], hn, ha0);
                        ha1 = fmaf(-sHB[mA + 2][n], hn, ha1);
                    }
                    sHA[mA][jA] = ha0;
                    sHA[mA + 2][jA] = ha1;
                }
            }
            __syncthreads();   // bar1: A, L, LR, HA, HB ready

            // ============ all threads: T = A P ; store blob[t] ============
            {
                float a0 = 0.f, a1 = 0.f, a2 = 0.f, a3 = 0.f;
#pragma unroll
                for (int k = 0; k < 16; k += 4) {
                    a0 = fmaf(sA[i][k + 0], sP[k + 0][j], a0);
                    a1 = fmaf(sA[i][k + 1], sP[k + 1][j], a1);
                    a2 = fmaf(sA[i][k + 2], sP[k + 2][j], a2);
                    a3 = fmaf(sA[i][k + 3], sP[k + 3][j], a3);
                }
                sT[i][j] = (a0 + a1) + (a2 + a3);
                float* base = blob + t * 400;
                int c4 = j >> 2, w = j & 3;
                base[(c4 * 20 + i) * 4 + w] = sA[i][j];
                if (j < 4) base[(4 * 20 + i) * 4 + j] = sL[i][j];
                if (i < 4) base[(c4 * 20 + 16 + i) * 4 + w] = sHA[i][j];
                if (i < 4 && j < 4) base[(4 * 20 + 16 + i) * 4 + j] = sHB[i][j];
            }
            __syncthreads();   // bar2: T ready

            // ============ all threads: P' = T A^T + LR L^T + Q ============
            int flag;
            {
                float a0 = sQ[i][j], a1 = 0.f, a2 = 0.f, a3 = 0.f;
#pragma unroll
                for (int k = 0; k < 16; k += 4) {
                    a0 = fmaf(sT[i][k + 0], sA[j][k + 0], a0);
                    a1 = fmaf(sT[i][k + 1], sA[j][k + 1], a1);
                    a2 = fmaf(sT[i][k + 2], sA[j][k + 2], a2);
                    a3 = fmaf(sT[i][k + 3], sA[j][k + 3], a3);
                }
                float acc = (a0 + a1) + (a2 + a3);
#pragma unroll
                for (int m = 0; m < 4; m++) acc = fmaf(sLR[i][m], sL[j][m], acc);
                float oldp = sP[i][j];
                flag = !(fabsf(acc - oldp) <= 1e-5f * fabsf(acc) + 1e-6f);
                sP[i][j] = acc;
            }
            if (!__syncthreads_or(flag)) {
                // converged: replicate fixed-point map for remaining steps
                int c4 = j >> 2, w = j & 3;
                for (int t2 = t + 1; t2 < NSTEP; ++t2) {
                    float* b2 = blob + t2 * 400;
                    b2[(c4 * 20 + i) * 4 + w] = sA[i][j];
                    if (j < 4) b2[(4 * 20 + i) * 4 + j] = sL[i][j];
                    if (i < 4) b2[(c4 * 20 + 16 + i) * 4 + w] = sHA[i][j];
                    if (i < 4 && j < 4) b2[(4 * 20 + 16 + i) * 4 + j] = sHB[i][j];
                }
                __syncthreads();
                if (tid == 0) {
                    __threadfence();
                    *(volatile int*)&g_ready = NCHUNK;
                }
                return;
            }
            if (((t + 1) % CH) == 0) {
                if (tid == 0) {
                    __threadfence();
                    *(volatile int*)&g_ready = (t + 1) / CH;
                }
            }
        }
        return;
    }

    // ==================== CONSUMERS: warp-per-batch scan =====================
    const int lane = tid & 31;
    const int b = ((blockIdx.x - 1) << 3) + (tid >> 5);
    const int g = (lane < 20) ? lane : 0;

    // wait for chunk 0 (also guarantees g_s0/g_y0 visible)
    if (tid == 0) {
        while (*(volatile int*)&g_ready < 1) __nanosleep(200);
        __threadfence();
    }
    __syncthreads();

    float x = (lane < 16) ? g_s0[lane] : 0.f;
    float* op = out + b * (NT * NM);
    const float* ip = inp + b * (NT * NM);
    if (lane >= 16 && lane < 20) op[lane - 16] = g_y0[lane - 16];

    const float4* gb = g_blob;
    int t = 0;
    float4 obn = *(const float4*)(ip);

#pragma unroll 1
    for (int c = 0; c < NCHUNK; ++c) {
        if (c > 0) {
            if (tid == 0) {
                while (*(volatile int*)&g_ready < c + 1) __nanosleep(200);
                __threadfence();
            }
            __syncthreads();
        }
        // stage chunk c into shared
#pragma unroll
        for (int r = 0; r < 6; r++) {
            int idx = tid + r * 256;
            if (idx < CHF4) sbuf[idx] = gb[c * CHF4 + idx];
        }
        __syncthreads();

        const float4* s4 = sbuf;
#pragma unroll 1
        for (int s = 0; s < CH; ++s, ++t) {
            float4 A[5];
#pragma unroll
            for (int cc = 0; cc < 5; cc++) A[cc] = s4[s * 100 + cc * 20 + g];
            float4 ob = obn;
            int tn = (t + 1 < NSTEP) ? t + 1 : t;
            obn = *(const float4*)(ip + tn * 4);
            KF_STEP(A, ob, t);
        }
        __syncthreads();  // all readers done before next chunk overwrites
    }
}

extern "C" void kernel_launch(void* const* d_in, const int* in_sizes, int n_in,
                              void* d_out, int out_size) {
    const float* inp = (const float*)d_in[0];
    const float* F   = (const float*)d_in[1];
    const float* H   = (const float*)d_in[2];
    const float* Q   = (const float*)d_in[3];
    const float* R   = (const float*)d_in[4];
    const float* x0  = (const float*)d_in[5];
    const float* sd  = (const float*)d_in[6];
    float* out = (float*)d_out;

    reset_kernel<<<1, 1>>>();
    fused_kernel<<<129, 256>>>(inp, out, F, H, Q, R, x0, sd);
}

// round 8
// speedup vs baseline: 1.1322x; 1.1322x over previous
#include <cuda_runtime.h>

#define NB 1024
#define NT 256
#define NS 16
#define NM 4
#define NSTEP 255
#define ROWF 20
#define CH 15            // chunk: 255 = 17 * 15
#define NCHUNK 17
#define CHF4 (CH * 100)  // float4 per chunk = 1500

// blob[t]: 100 float4 per step, float4-column-major:
//   f4 index (c*20 + row): row<16 state rows, row 16+m measurement rows.
//   Column block c<4 covers matrix cols 4c..4c+3; c==4 covers cols 16..19 (L/HB).
__device__ float4 g_blob[NSTEP * 100];
__device__ float  g_s0[16];
__device__ float  g_y0[4];
__device__ int    g_ready;   // chunks published (monotonic within a launch)

__global__ void reset_kernel() { g_ready = 0; }

// ---------------------------------------------------------------------------
// KF consumer step: lanes 0..15 new state, lanes 16..19 write output.
// ---------------------------------------------------------------------------
#define KF_STEP(Ab, ob, tt)                                                    \
    do {                                                                       \
        float acc0, acc1, res;                                                 \
        acc0 = (Ab)[0].x * __shfl_sync(0xffffffffu, x, 0);                     \
        acc1 = (Ab)[0].y * __shfl_sync(0xffffffffu, x, 1);                     \
        acc0 = fmaf((Ab)[0].z, __shfl_sync(0xffffffffu, x, 2), acc0);          \
        acc1 = fmaf((Ab)[0].w, __shfl_sync(0xffffffffu, x, 3), acc1);          \
        acc0 = fmaf((Ab)[1].x, __shfl_sync(0xffffffffu, x, 4), acc0);          \
        acc1 = fmaf((Ab)[1].y, __shfl_sync(0xffffffffu, x, 5), acc1);          \
        acc0 = fmaf((Ab)[1].z, __shfl_sync(0xffffffffu, x, 6), acc0);          \
        acc1 = fmaf((Ab)[1].w, __shfl_sync(0xffffffffu, x, 7), acc1);          \
        acc0 = fmaf((Ab)[2].x, __shfl_sync(0xffffffffu, x, 8), acc0);          \
        acc1 = fmaf((Ab)[2].y, __shfl_sync(0xffffffffu, x, 9), acc1);          \
        acc0 = fmaf((Ab)[2].z, __shfl_sync(0xffffffffu, x, 10), acc0);         \
        acc1 = fmaf((Ab)[2].w, __shfl_sync(0xffffffffu, x, 11), acc1);         \
        acc0 = fmaf((Ab)[3].x, __shfl_sync(0xffffffffu, x, 12), acc0);         \
        acc1 = fmaf((Ab)[3].y, __shfl_sync(0xffffffffu, x, 13), acc1);         \
        acc0 = fmaf((Ab)[3].z, __shfl_sync(0xffffffffu, x, 14), acc0);         \
        acc1 = fmaf((Ab)[3].w, __shfl_sync(0xffffffffu, x, 15), acc1);         \
        acc0 = fmaf((Ab)[4].x, (ob).x, acc0);                                  \
        acc1 = fmaf((Ab)[4].y, (ob).y, acc1);                                  \
        acc0 = fmaf((Ab)[4].z, (ob).z, acc0);                                  \
        acc1 = fmaf((Ab)[4].w, (ob).w, acc1);                                  \
        res = acc0 + acc1;                                                     \
        if (lane < 16) x = res;                                                \
        else if (lane < 20) op[((tt) + 1) * 4 + (lane - 16)] = res;            \
    } while (0)

__global__ __launch_bounds__(256, 1) void fused_kernel(
    const float* __restrict__ inp, float* __restrict__ out,
    const float* __restrict__ F, const float* __restrict__ H,
    const float* __restrict__ Q, const float* __restrict__ R,
    const float* __restrict__ x0, const float* __restrict__ sd)
{
    // producer shared state (R5-proven structure)
    __shared__ float sP[16][ROWF];
    __shared__ float sT[16][ROWF];
    __shared__ float sA[16][ROWF];
    __shared__ float sF[16][ROWF];
    __shared__ float sQ[16][ROWF];
    __shared__ float sH[4][ROWF];
    __shared__ float sHP[4][ROWF];
    __shared__ float sHA[4][ROWF];
    __shared__ __align__(16) float sFHP[16][4];
    __shared__ __align__(16) float sL[16][4];
    __shared__ __align__(16) float sLR[16][4];
    __shared__ float sS[4][4], sSi[4][4], scof[4][4], sR[4][4], sHB[4][4];
    __shared__ float ssd2[16], ss0[16], srdet;
    // consumer staging buffers
    __shared__ __align__(16) float4 sbuf[CHF4];   // 24 KB
    __shared__ __align__(16) float4 sobs[8][16];  // 15 used per warp

    const int tid = threadIdx.x;

    if (blockIdx.x == 0) {
        // ================= PRODUCER: R5 Joseph Riccati, 6 barriers ==========
        const int i = tid >> 4, j = tid & 15;

        sF[i][j] = F[i * 16 + j];
        sQ[i][j] = Q[i * 16 + j];
        if (i < 4) sH[i][j] = H[i * 16 + j];
        if (tid < 16) {
            sR[tid >> 2][tid & 3] = R[tid];
            float v = sd[tid];
            ssd2[tid] = v * v;
        }
        __syncthreads();

        // P = F diag(sd^2) F^T + Q ; s0 = F x0 ; y0 = H s0
        {
            float a0 = sQ[i][j], a1 = 0.f, a2 = 0.f, a3 = 0.f;
#pragma unroll
            for (int k = 0; k < 16; k += 4) {
                a0 = fmaf(sF[i][k + 0] * ssd2[k + 0], sF[j][k + 0], a0);
                a1 = fmaf(sF[i][k + 1] * ssd2[k + 1], sF[j][k + 1], a1);
                a2 = fmaf(sF[i][k + 2] * ssd2[k + 2], sF[j][k + 2], a2);
                a3 = fmaf(sF[i][k + 3] * ssd2[k + 3], sF[j][k + 3], a3);
            }
            sP[i][j] = (a0 + a1) + (a2 + a3);
        }
        if (tid < 16) {
            float acc = 0.f;
#pragma unroll
            for (int k = 0; k < 16; k++) acc = fmaf(sF[tid][k], x0[k], acc);
            ss0[tid] = acc;
            g_s0[tid] = acc;
        }
        __syncthreads();
        if (tid < 4) {
            float acc = 0.f;
#pragma unroll
            for (int k = 0; k < 16; k++) acc = fmaf(sH[tid][k], ss0[k], acc);
            g_y0[tid] = acc;
        }

        float* blob = (float*)g_blob;

#pragma unroll 1
        for (int t = 0; t < NSTEP; ++t) {
            // stage1: HP = H P (64 threads)
            if (tid < 64) {
                int m = tid >> 4, jj = tid & 15;
                float a0 = 0.f, a1 = 0.f, a2 = 0.f, a3 = 0.f;
#pragma unroll
                for (int k = 0; k < 16; k += 4) {
                    a0 = fmaf(sH[m][k + 0], sP[k + 0][jj], a0);
                    a1 = fmaf(sH[m][k + 1], sP[k + 1][jj], a1);
                    a2 = fmaf(sH[m][k + 2], sP[k + 2][jj], a2);
                    a3 = fmaf(sH[m][k + 3], sP[k + 3][jj], a3);
                }
                sHP[m][jj] = (a0 + a1) + (a2 + a3);
            }
            __syncthreads();

            // stage2: warp0 (tid<16): S = HP H^T + R, 4x4 cofactor inverse.
            //         threads 64..127: FHP[i][n] = sum_k F[i][k] * HP[n][k]
            if (tid < 16) {
                int m = tid >> 2, n = tid & 3;
                float acc = sR[m][n];
#pragma unroll
                for (int k = 0; k < 16; k++) acc = fmaf(sHP[m][k], sH[n][k], acc);
                sS[m][n] = acc;
                __syncwarp(0xffffu);
                int r0 = 0 + (0 >= m), r1 = 1 + (1 >= m), r2 = 2 + (2 >= m);
                int c0 = 0 + (0 >= n), c1 = 1 + (1 >= n), c2 = 2 + (2 >= n);
                float a = sS[r0][c0], b = sS[r0][c1], c = sS[r0][c2];
                float d = sS[r1][c0], e = sS[r1][c1], f = sS[r1][c2];
                float g = sS[r2][c0], h = sS[r2][c1], i2 = sS[r2][c2];
                float minor = a * (e * i2 - f * h) - b * (d * i2 - f * g) + c * (d * h - e * g);
                scof[m][n] = ((m + n) & 1) ? -minor : minor;
                __syncwarp(0xffffu);
                if (tid == 0) {
                    float det = sS[0][0] * scof[0][0] + sS[0][1] * scof[0][1] +
                                sS[0][2] * scof[0][2] + sS[0][3] * scof[0][3];
                    srdet = __fdividef(1.f, det);
                }
                __syncwarp(0xffffu);
                sSi[m][n] = scof[n][m] * srdet;   // Sinv = adj(S)/det
            }
            if (tid >= 64 && tid < 128) {
                int ii = (tid - 64) >> 2, n = (tid - 64) & 3;
                float a0 = 0.f, a1 = 0.f, a2 = 0.f, a3 = 0.f;
#pragma unroll
                for (int k = 0; k < 16; k += 4) {
                    a0 = fmaf(sF[ii][k + 0], sHP[n][k + 0], a0);
                    a1 = fmaf(sF[ii][k + 1], sHP[n][k + 1], a1);
                    a2 = fmaf(sF[ii][k + 2], sHP[n][k + 2], a2);
                    a3 = fmaf(sF[ii][k + 3], sHP[n][k + 3], a3);
                }
                sFHP[ii][n] = (a0 + a1) + (a2 + a3);
            }
            __syncthreads();

            // stage3: L[i][m] = sum_n FHP[i][n] * Sinv[n][m]   ( = F K )
            if (tid < 64) {
                int ii = tid >> 2, m = tid & 3;
                float acc = 0.f;
#pragma unroll
                for (int n = 0; n < 4; n++) acc = fmaf(sFHP[ii][n], sSi[n][m], acc);
                sL[ii][m] = acc;
            }
            __syncthreads();

            // stage5: A = F - L H (all), LR = L R (threads 64..127)
            {
                float acc = sF[i][j];
#pragma unroll
                for (int m = 0; m < 4; m++) acc = fmaf(-sL[i][m], sH[m][j], acc);
                sA[i][j] = acc;
            }
            if (tid >= 64 && tid < 128) {
                int ii = (tid - 64) >> 2, m = (tid - 64) & 3;
                float acc = 0.f;
#pragma unroll
                for (int n = 0; n < 4; n++) acc = fmaf(sL[ii][n], sR[n][m], acc);
                sLR[ii][m] = acc;
            }
            __syncthreads();

            // stage6: T1 = A P (all); HA = H A (tid<64); HB = H L (tid 64..79)
            {
                float a0 = 0.f, a1 = 0.f, a2 = 0.f, a3 = 0.f;
#pragma unroll
                for (int k = 0; k < 16; k += 4) {
                    a0 = fmaf(sA[i][k + 0], sP[k + 0][j], a0);
                    a1 = fmaf(sA[i][k + 1], sP[k + 1][j], a1);
                    a2 = fmaf(sA[i][k + 2], sP[k + 2][j], a2);
                    a3 = fmaf(sA[i][k + 3], sP[k + 3][j], a3);
                }
                sT[i][j] = (a0 + a1) + (a2 + a3);
            }
            if (tid < 64) {
                int m = tid >> 4, jj = tid & 15;
                float acc = 0.f;
#pragma unroll
                for (int k = 0; k < 16; k++) acc = fmaf(sH[m][k], sA[k][jj], acc);
                sHA[m][jj] = acc;
            } else if (tid < 80) {
                int m = (tid - 64) >> 2, n = (tid - 64) & 3;
                float acc = 0.f;
#pragma unroll
                for (int k = 0; k < 16; k++) acc = fmaf(sH[m][k], sL[k][n], acc);
                sHB[m][n] = acc;
            }
            __syncthreads();

            // stage7: P' = T1 A^T + LR L^T + Q ; store blob[t] ; convergence
            int flag;
            {
                float a0 = sQ[i][j], a1 = 0.f, a2 = 0.f, a3 = 0.f;
#pragma unroll
                for (int k = 0; k < 16; k += 4) {
                    a0 = fmaf(sT[i][k + 0], sA[j][k + 0], a0);
                    a1 = fmaf(sT[i][k + 1], sA[j][k + 1], a1);
                    a2 = fmaf(sT[i][k + 2], sA[j][k + 2], a2);
                    a3 = fmaf(sT[i][k + 3], sA[j][k + 3], a3);
                }
                float acc = (a0 + a1) + (a2 + a3);
#pragma unroll
                for (int m = 0; m < 4; m++) acc = fmaf(sLR[i][m], sL[j][m], acc);
                float* base = blob + t * 400;
                int c4 = j >> 2, w = j & 3;
                base[(c4 * 20 + i) * 4 + w] = sA[i][j];
                if (j < 4) base[(4 * 20 + i) * 4 + j] = sL[i][j];
                if (i < 4) base[(c4 * 20 + 16 + i) * 4 + w] = sHA[i][j];
                if (i < 4 && j < 4) base[(4 * 20 + 16 + i) * 4 + j] = sHB[i][j];
                float oldp = sP[i][j];
                // NaN-safe (NaN -> flag=1); threshold above fp32 jitter floor.
                flag = !(fabsf(acc - oldp) <= 1e-5f * fabsf(acc) + 1e-6f);
                sP[i][j] = acc;
            }
            if (!__syncthreads_or(flag)) {
                // converged: replicate fixed-point map for remaining steps
                int c4 = j >> 2, w = j & 3;
                for (int t2 = t + 1; t2 < NSTEP; ++t2) {
                    float* b2 = blob + t2 * 400;
                    b2[(c4 * 20 + i) * 4 + w] = sA[i][j];
                    if (j < 4) b2[(4 * 20 + i) * 4 + j] = sL[i][j];
                    if (i < 4) b2[(c4 * 20 + 16 + i) * 4 + w] = sHA[i][j];
                    if (i < 4 && j < 4) b2[(4 * 20 + 16 + i) * 4 + j] = sHB[i][j];
                }
                __syncthreads();
                if (tid == 0) {
                    __threadfence();
                    *(volatile int*)&g_ready = NCHUNK;
                }
                return;
            }
            if (((t + 1) % CH) == 0) {
                if (tid == 0) {
                    __threadfence();
                    *(volatile int*)&g_ready = (t + 1) / CH;
                }
            }
        }
        return;
    }

    // ==================== CONSUMERS: warp-per-batch scan =====================
    const int lane = tid & 31;
    const int wrp = tid >> 5;
    const int b = ((blockIdx.x - 1) << 3) + wrp;
    const int g = (lane < 20) ? lane : 0;

    // wait for chunk 0 (also guarantees g_s0/g_y0 visible)
    if (tid == 0) {
        while (*(volatile int*)&g_ready < 1) __nanosleep(200);
        __threadfence();
    }
    __syncthreads();

    float x = (lane < 16) ? g_s0[lane] : 0.f;
    float* op = out + b * (NT * NM);
    if (lane >= 16 && lane < 20) op[lane - 16] = g_y0[lane - 16];

    const float4* gb = g_blob;
    const int bb = (blockIdx.x - 1) << 3;

#pragma unroll 1
    for (int c = 0; c < NCHUNK; ++c) {
        if (c > 0) {
            if (tid == 0) {
                while (*(volatile int*)&g_ready < c + 1) __nanosleep(200);
                __threadfence();
            }
            __syncthreads();
        }
        // stage chunk c blob + this block's obs into shared
#pragma unroll
        for (int r = 0; r < 6; r++) {
            int idx = tid + r * 256;
            if (idx < CHF4) sbuf[idx] = gb[c * CHF4 + idx];
        }
        if (tid < 8 * CH) {
            int w = tid / CH, s = tid - w * CH;
            int tt = c * CH + s;   // <= 254
            sobs[w][s] = *(const float4*)(inp + ((bb + w) * NT + tt) * 4);
        }
        __syncthreads();

        const float4* s4 = sbuf;
        int t = c * CH;
#pragma unroll 1
        for (int s = 0; s < CH; ++s, ++t) {
            float4 A[5];
#pragma unroll
            for (int cc = 0; cc < 5; cc++) A[cc] = s4[s * 100 + cc * 20 + g];
            float4 ob = sobs[wrp][s];
            KF_STEP(A, ob, t);
        }
        __syncthreads();  // all readers done before next chunk overwrites
    }
}

extern "C" void kernel_launch(void* const* d_in, const int* in_sizes, int n_in,
                              void* d_out, int out_size) {
    const float* inp = (const float*)d_in[0];
    const float* F   = (const float*)d_in[1];
    const float* H   = (const float*)d_in[2];
    const float* Q   = (const float*)d_in[3];
    const float* R   = (const float*)d_in[4];
    const float* x0  = (const float*)d_in[5];
    const float* sd  = (const float*)d_in[6];
    float* out = (float*)d_out;

    reset_kernel<<<1, 1>>>();
    fused_kernel<<<129, 256>>>(inp, out, F, H, Q, R, x0, sd);
}

// round 9
// speedup vs baseline: 1.2901x; 1.1394x over previous
#include <cuda_runtime.h>

#define NB 1024
#define NT 256
#define NS 16
#define NM 4
#define NSTEP 255
#define ROWF 20
#define CH 15            // chunk: 255 = 17 * 15
#define NCHUNK 17
#define CHF4 (CH * 100)  // float4 per chunk = 1500

// blob[t]: 100 float4 per step, float4-column-major:
//   f4 index (c*20 + row): row<16 state rows, row 16+m measurement rows.
//   Column block c<4 covers matrix cols 4c..4c+3; c==4 covers cols 16..19 (L/HB).
__device__ float4 g_blob[NSTEP * 100];
__device__ float  g_s0[16];
__device__ float  g_y0[4];
__device__ int    g_ready;   // chunks published (monotonic within a launch)

__global__ void reset_kernel() { g_ready = 0; }

// ---------------------------------------------------------------------------
// KF consumer step: lanes 0..15 new state, lanes 16..19 write output.
// ---------------------------------------------------------------------------
#define KF_STEP(Ab, ob, tt)                                                    \
    do {                                                                       \
        float acc0, acc1, res;                                                 \
        acc0 = (Ab)[0].x * __shfl_sync(0xffffffffu, x, 0);                     \
        acc1 = (Ab)[0].y * __shfl_sync(0xffffffffu, x, 1);                     \
        acc0 = fmaf((Ab)[0].z, __shfl_sync(0xffffffffu, x, 2), acc0);          \
        acc1 = fmaf((Ab)[0].w, __shfl_sync(0xffffffffu, x, 3), acc1);          \
        acc0 = fmaf((Ab)[1].x, __shfl_sync(0xffffffffu, x, 4), acc0);          \
        acc1 = fmaf((Ab)[1].y, __shfl_sync(0xffffffffu, x, 5), acc1);          \
        acc0 = fmaf((Ab)[1].z, __shfl_sync(0xffffffffu, x, 6), acc0);          \
        acc1 = fmaf((Ab)[1].w, __shfl_sync(0xffffffffu, x, 7), acc1);          \
        acc0 = fmaf((Ab)[2].x, __shfl_sync(0xffffffffu, x, 8), acc0);          \
        acc1 = fmaf((Ab)[2].y, __shfl_sync(0xffffffffu, x, 9), acc1);          \
        acc0 = fmaf((Ab)[2].z, __shfl_sync(0xffffffffu, x, 10), acc0);         \
        acc1 = fmaf((Ab)[2].w, __shfl_sync(0xffffffffu, x, 11), acc1);         \
        acc0 = fmaf((Ab)[3].x, __shfl_sync(0xffffffffu, x, 12), acc0);         \
        acc1 = fmaf((Ab)[3].y, __shfl_sync(0xffffffffu, x, 13), acc1);         \
        acc0 = fmaf((Ab)[3].z, __shfl_sync(0xffffffffu, x, 14), acc0);         \
        acc1 = fmaf((Ab)[3].w, __shfl_sync(0xffffffffu, x, 15), acc1);         \
        acc0 = fmaf((Ab)[4].x, (ob).x, acc0);                                  \
        acc1 = fmaf((Ab)[4].y, (ob).y, acc1);                                  \
        acc0 = fmaf((Ab)[4].z, (ob).z, acc0);                                  \
        acc1 = fmaf((Ab)[4].w, (ob).w, acc1);                                  \
        res = acc0 + acc1;                                                     \
        if (lane < 16) x = res;                                                \
        else if (lane < 20) op[((tt) + 1) * 4 + (lane - 16)] = res;            \
    } while (0)

__global__ __launch_bounds__(256, 1) void fused_kernel(
    const float* __restrict__ inp, float* __restrict__ out,
    const float* __restrict__ F, const float* __restrict__ H,
    const float* __restrict__ Q, const float* __restrict__ R,
    const float* __restrict__ x0, const float* __restrict__ sd)
{
    // producer shared state
    __shared__ float sP[16][ROWF];
    __shared__ float sT[16][ROWF];
    __shared__ float sA[16][ROWF];
    __shared__ float sF[16][ROWF];
    __shared__ float sQ[16][ROWF];
    __shared__ float sH[4][ROWF];
    __shared__ float sHP[4][ROWF];
    __shared__ float sHA[4][ROWF];
    __shared__ __align__(16) float sFHP[16][4];
    __shared__ __align__(16) float sL[16][4];
    __shared__ __align__(16) float sLR[16][4];
    __shared__ float sS[4][4], sSi[4][4], scof[4][4], sR[4][4], sHB[4][4];
    __shared__ float ssd2[16], ss0[16], srdet;
    // consumer staging buffers
    __shared__ __align__(16) float4 sbuf[CHF4];   // 24 KB
    __shared__ __align__(16) float4 sobs[8][16];  // 15 used per warp

    const int tid = threadIdx.x;

    if (blockIdx.x == 0) {
        // ============ PRODUCER: Joseph Riccati, 5 barriers/step ============
        const int i = tid >> 4, j = tid & 15;

        sF[i][j] = F[i * 16 + j];
        sQ[i][j] = Q[i * 16 + j];
        if (i < 4) sH[i][j] = H[i * 16 + j];
        if (tid < 16) {
            sR[tid >> 2][tid & 3] = R[tid];
            float v = sd[tid];
            ssd2[tid] = v * v;
        }
        __syncthreads();

        // P = F diag(sd^2) F^T + Q ; s0 = F x0 ; y0 = H s0
        {
            float a0 = sQ[i][j], a1 = 0.f, a2 = 0.f, a3 = 0.f;
#pragma unroll
            for (int k = 0; k < 16; k += 4) {
                a0 = fmaf(sF[i][k + 0] * ssd2[k + 0], sF[j][k + 0], a0);
                a1 = fmaf(sF[i][k + 1] * ssd2[k + 1], sF[j][k + 1], a1);
                a2 = fmaf(sF[i][k + 2] * ssd2[k + 2], sF[j][k + 2], a2);
                a3 = fmaf(sF[i][k + 3] * ssd2[k + 3], sF[j][k + 3], a3);
            }
            sP[i][j] = (a0 + a1) + (a2 + a3);
        }
        if (tid < 16) {
            float acc = 0.f;
#pragma unroll
            for (int k = 0; k < 16; k++) acc = fmaf(sF[tid][k], x0[k], acc);
            ss0[tid] = acc;
            g_s0[tid] = acc;
        }
        __syncthreads();
        if (tid < 4) {
            float acc = 0.f;
#pragma unroll
            for (int k = 0; k < 16; k++) acc = fmaf(sH[tid][k], ss0[k], acc);
            g_y0[tid] = acc;
        }

        float* blob = (float*)g_blob;
        const int c4 = j >> 2, w = j & 3;

#pragma unroll 1
        for (int t = 0; t < NSTEP; ++t) {
            float* base = blob + t * 400;

            // stage1: HP = H P (64 threads)
            if (tid < 64) {
                int m = tid >> 4, jj = tid & 15;
                float a0 = 0.f, a1 = 0.f, a2 = 0.f, a3 = 0.f;
#pragma unroll
                for (int k = 0; k < 16; k += 4) {
                    a0 = fmaf(sH[m][k + 0], sP[k + 0][jj], a0);
                    a1 = fmaf(sH[m][k + 1], sP[k + 1][jj], a1);
                    a2 = fmaf(sH[m][k + 2], sP[k + 2][jj], a2);
                    a3 = fmaf(sH[m][k + 3], sP[k + 3][jj], a3);
                }
                sHP[m][jj] = (a0 + a1) + (a2 + a3);
            }
            __syncthreads();   // bar1

            // stage2: warp0 (tid<16): S = HP H^T + R, cofactor inverse.
            //         threads 64..127: FHP[i][n] = sum_k F[i][k] * HP[n][k]
            if (tid < 16) {
                int m = tid >> 2, n = tid & 3;
                float acc = sR[m][n];
#pragma unroll
                for (int k = 0; k < 16; k++) acc = fmaf(sHP[m][k], sH[n][k], acc);
                sS[m][n] = acc;
                __syncwarp(0xffffu);
                int r0 = 0 + (0 >= m), r1 = 1 + (1 >= m), r2 = 2 + (2 >= m);
                int c0 = 0 + (0 >= n), c1 = 1 + (1 >= n), c2 = 2 + (2 >= n);
                float a = sS[r0][c0], b = sS[r0][c1], c = sS[r0][c2];
                float d = sS[r1][c0], e = sS[r1][c1], f = sS[r1][c2];
                float g = sS[r2][c0], h = sS[r2][c1], i2 = sS[r2][c2];
                float minor = a * (e * i2 - f * h) - b * (d * i2 - f * g) + c * (d * h - e * g);
                scof[m][n] = ((m + n) & 1) ? -minor : minor;
                __syncwarp(0xffffu);
                if (tid == 0) {
                    float det = sS[0][0] * scof[0][0] + sS[0][1] * scof[0][1] +
                                sS[0][2] * scof[0][2] + sS[0][3] * scof[0][3];
                    srdet = __fdividef(1.f, det);
                }
                __syncwarp(0xffffu);
                sSi[m][n] = scof[n][m] * srdet;   // Sinv = adj(S)/det
            }
            if (tid >= 64 && tid < 128) {
                int ii = (tid - 64) >> 2, n = (tid - 64) & 3;
                float a0 = 0.f, a1 = 0.f, a2 = 0.f, a3 = 0.f;
#pragma unroll
                for (int k = 0; k < 16; k += 4) {
                    a0 = fmaf(sF[ii][k + 0], sHP[n][k + 0], a0);
                    a1 = fmaf(sF[ii][k + 1], sHP[n][k + 1], a1);
                    a2 = fmaf(sF[ii][k + 2], sHP[n][k + 2], a2);
                    a3 = fmaf(sF[ii][k + 3], sHP[n][k + 3], a3);
                }
                sFHP[ii][n] = (a0 + a1) + (a2 + a3);
            }
            __syncthreads();   // bar2

            // stage3': merged. All threads: A[i][j] = F - FHP*(Si*H) (redundant SiH).
            //          tid 64..127: L = FHP*Si. tid 128..191: LR = FHP*(Si*R).
            //          Blob stores of A, L issue here (register-sourced).
            {
                float sih0, sih1, sih2, sih3;
                {
                    float hj0 = sH[0][j], hj1 = sH[1][j], hj2 = sH[2][j], hj3 = sH[3][j];
                    sih0 = sSi[0][0] * hj0;
                    sih1 = sSi[1][0] * hj0;
                    sih2 = sSi[2][0] * hj0;
                    sih3 = sSi[3][0] * hj0;
                    sih0 = fmaf(sSi[0][1], hj1, sih0);
                    sih1 = fmaf(sSi[1][1], hj1, sih1);
                    sih2 = fmaf(sSi[2][1], hj1, sih2);
                    sih3 = fmaf(sSi[3][1], hj1, sih3);
                    sih0 = fmaf(sSi[0][2], hj2, sih0);
                    sih1 = fmaf(sSi[1][2], hj2, sih1);
                    sih2 = fmaf(sSi[2][2], hj2, sih2);
                    sih3 = fmaf(sSi[3][2], hj2, sih3);
                    sih0 = fmaf(sSi[0][3], hj3, sih0);
                    sih1 = fmaf(sSi[1][3], hj3, sih1);
                    sih2 = fmaf(sSi[2][3], hj3, sih2);
                    sih3 = fmaf(sSi[3][3], hj3, sih3);
                }
                float a = sF[i][j];
                a = fmaf(-sFHP[i][0], sih0, a);
                a = fmaf(-sFHP[i][1], sih1, a);
                a = fmaf(-sFHP[i][2], sih2, a);
                a = fmaf(-sFHP[i][3], sih3, a);
                sA[i][j] = a;
                base[(c4 * 20 + i) * 4 + w] = a;
            }
            if (tid >= 64 && tid < 128) {
                int ii = (tid - 64) >> 2, m = (tid - 64) & 3;
                float acc = 0.f;
#pragma unroll
                for (int n = 0; n < 4; n++) acc = fmaf(sFHP[ii][n], sSi[n][m], acc);
                sL[ii][m] = acc;
                base[(4 * 20 + ii) * 4 + m] = acc;
            } else if (tid >= 128 && tid < 192) {
                int ii = (tid - 128) >> 2, m = (tid - 128) & 3;
                float sir0 = 0.f, sir1 = 0.f, sir2 = 0.f, sir3 = 0.f;
#pragma unroll
                for (int n = 0; n < 4; n++) {
                    float rn = sR[n][m];
                    sir0 = fmaf(sSi[0][n], rn, sir0);
                    sir1 = fmaf(sSi[1][n], rn, sir1);
                    sir2 = fmaf(sSi[2][n], rn, sir2);
                    sir3 = fmaf(sSi[3][n], rn, sir3);
                }
                float acc = sFHP[ii][0] * sir0;
                acc = fmaf(sFHP[ii][1], sir1, acc);
                acc = fmaf(sFHP[ii][2], sir2, acc);
                acc = fmaf(sFHP[ii][3], sir3, acc);
                sLR[ii][m] = acc;
            }
            __syncthreads();   // bar3

            // stage4': T = A P (all); HA = H A (tid<64); HB = H L (tid 64..79)
            {
                float a0 = 0.f, a1 = 0.f, a2 = 0.f, a3 = 0.f;
#pragma unroll
                for (int k = 0; k < 16; k += 4) {
                    a0 = fmaf(sA[i][k + 0], sP[k + 0][j], a0);
                    a1 = fmaf(sA[i][k + 1], sP[k + 1][j], a1);
                    a2 = fmaf(sA[i][k + 2], sP[k + 2][j], a2);
                    a3 = fmaf(sA[i][k + 3], sP[k + 3][j], a3);
                }
                sT[i][j] = (a0 + a1) + (a2 + a3);
            }
            if (tid < 64) {
                int m = tid >> 4, jj = tid & 15;
                float acc = 0.f;
#pragma unroll
                for (int k = 0; k < 16; k++) acc = fmaf(sH[m][k], sA[k][jj], acc);
                sHA[m][jj] = acc;
            } else if (tid < 80) {
                int m = (tid - 64) >> 2, n = (tid - 64) & 3;
                float acc = 0.f;
#pragma unroll
                for (int k = 0; k < 16; k++) acc = fmaf(sH[m][k], sL[k][n], acc);
                sHB[m][n] = acc;
            }
            __syncthreads();   // bar4

            // stage5': P' = T A^T + LR L^T + Q ; HA/HB blob ; convergence
            int flag;
            {
                float a0 = sQ[i][j], a1 = 0.f, a2 = 0.f, a3 = 0.f;
#pragma unroll
                for (int k = 0; k < 16; k += 4) {
                    a0 = fmaf(sT[i][k + 0], sA[j][k + 0], a0);
                    a1 = fmaf(sT[i][k + 1], sA[j][k + 1], a1);
                    a2 = fmaf(sT[i][k + 2], sA[j][k + 2], a2);
                    a3 = fmaf(sT[i][k + 3], sA[j][k + 3], a3);
                }
                float acc = (a0 + a1) + (a2 + a3);
#pragma unroll
                for (int m = 0; m < 4; m++) acc = fmaf(sLR[i][m], sL[j][m], acc);
                if (i < 4) base[(c4 * 20 + 16 + i) * 4 + w] = sHA[i][j];
                if (i < 4 && j < 4) base[(4 * 20 + 16 + i) * 4 + j] = sHB[i][j];
                float oldp = sP[i][j];
                // NaN-safe (NaN -> flag=1)
                flag = !(fabsf(acc - oldp) <= 1e-4f * fabsf(acc) + 1e-5f);
                sP[i][j] = acc;
            }
            if (!__syncthreads_or(flag)) {   // bar5 (loop barrier)
                // converged: replicate fixed-point map for remaining steps
                for (int t2 = t + 1; t2 < NSTEP; ++t2) {
                    float* b2 = blob + t2 * 400;
                    b2[(c4 * 20 + i) * 4 + w] = sA[i][j];
                    if (j < 4) b2[(4 * 20 + i) * 4 + j] = sL[i][j];
                    if (i < 4) b2[(c4 * 20 + 16 + i) * 4 + w] = sHA[i][j];
                    if (i < 4 && j < 4) b2[(4 * 20 + 16 + i) * 4 + j] = sHB[i][j];
                }
                __syncthreads();
                if (tid == 0) {
                    __threadfence();
                    *(volatile int*)&g_ready = NCHUNK;
                }
                return;
            }
            if (((t + 1) % CH) == 0) {
                if (tid == 0) {
                    __threadfence();
                    *(volatile int*)&g_ready = (t + 1) / CH;
                }
            }
        }
        return;
    }

    // ==================== CONSUMERS: warp-per-batch scan =====================
    const int lane = tid & 31;
    const int wrp = tid >> 5;
    const int b = ((blockIdx.x - 1) << 3) + wrp;
    const int g = (lane < 20) ? lane : 0;

    // wait for chunk 0 (also guarantees g_s0/g_y0 visible)
    if (tid == 0) {
        while (*(volatile int*)&g_ready < 1) __nanosleep(200);
        __threadfence();
    }
    __syncthreads();

    float x = (lane < 16) ? g_s0[lane] : 0.f;
    float* op = out + b * (NT * NM);
    if (lane >= 16 && lane < 20) op[lane - 16] = g_y0[lane - 16];

    const float4* gb = g_blob;
    const int bb = (blockIdx.x - 1) << 3;

#pragma unroll 1
    for (int c = 0; c < NCHUNK; ++c) {
        if (c > 0) {
            if (tid == 0) {
                while (*(volatile int*)&g_ready < c + 1) __nanosleep(200);
                __threadfence();
            }
            __syncthreads();
        }
        // stage chunk c blob + this block's obs into shared
#pragma unroll
        for (int r = 0; r < 6; r++) {
            int idx = tid + r * 256;
            if (idx < CHF4) sbuf[idx] = gb[c * CHF4 + idx];
        }
        if (tid < 8 * CH) {
            int w2 = tid / CH, s = tid - w2 * CH;
            int tt = c * CH + s;   // <= 254
            sobs[w2][s] = *(const float4*)(inp + ((bb + w2) * NT + tt) * 4);
        }
        __syncthreads();

        const float4* s4 = sbuf;
        int t = c * CH;
#pragma unroll 1
        for (int s = 0; s < CH; ++s, ++t) {
            float4 A[5];
#pragma unroll
            for (int cc = 0; cc < 5; cc++) A[cc] = s4[s * 100 + cc * 20 + g];
            float4 ob = sobs[wrp][s];
            KF_STEP(A, ob, t);
        }
        __syncthreads();  // all readers done before next chunk overwrites
    }
}

extern "C" void kernel_launch(void* const* d_in, const int* in_sizes, int n_in,
                              void* d_out, int out_size) {
    const float* inp = (const float*)d_in[0];
    const float* F   = (const float*)d_in[1];
    const float* H   = (const float*)d_in[2];
    const float* Q   = (const float*)d_in[3];
    const float* R   = (const float*)d_in[4];
    const float* x0  = (const float*)d_in[5];
    const float* sd  = (const float*)d_in[6];
    float* out = (float*)d_out;

    reset_kernel<<<1, 1>>>();
    fused_kernel<<<129, 256>>>(inp, out, F, H, Q, R, x0, sd);
}

// round 10
// speedup vs baseline: 1.4503x; 1.1242x over previous
#include <cuda_runtime.h>

#define NB 1024
#define NT 256
#define NS 16
#define NM 4
#define NSTEP 255
#define ROWF 20
#define CH 15            // chunk: 255 = 17 * 15
#define NCHUNK 17
#define CHF4 (CH * 100)  // float4 per chunk = 1500

// blob[t]: 100 float4 per step, float4-column-major:
//   f4 index (c*20 + row): row<16 state rows, row 16+m measurement rows.
//   Column block c<4 covers matrix cols 4c..4c+3; c==4 covers cols 16..19 (L/HB).
__device__ float4 g_blob[NSTEP * 100];
__device__ float  g_s0[16];
__device__ float  g_y0[4];
__device__ int    g_ready;   // chunks published (monotonic within a launch)

__global__ void reset_kernel() { g_ready = 0; }

// ---------------------------------------------------------------------------
// KF consumer step: lanes 0..15 new state, lanes 16..19 write output.
// ---------------------------------------------------------------------------
#define KF_STEP(Ab, ob, tt)                                                    \
    do {                                                                       \
        float acc0, acc1, res;                                                 \
        acc0 = (Ab)[0].x * __shfl_sync(0xffffffffu, x, 0);                     \
        acc1 = (Ab)[0].y * __shfl_sync(0xffffffffu, x, 1);                     \
        acc0 = fmaf((Ab)[0].z, __shfl_sync(0xffffffffu, x, 2), acc0);          \
        acc1 = fmaf((Ab)[0].w, __shfl_sync(0xffffffffu, x, 3), acc1);          \
        acc0 = fmaf((Ab)[1].x, __shfl_sync(0xffffffffu, x, 4), acc0);          \
        acc1 = fmaf((Ab)[1].y, __shfl_sync(0xffffffffu, x, 5), acc1);          \
        acc0 = fmaf((Ab)[1].z, __shfl_sync(0xffffffffu, x, 6), acc0);          \
        acc1 = fmaf((Ab)[1].w, __shfl_sync(0xffffffffu, x, 7), acc1);          \
        acc0 = fmaf((Ab)[2].x, __shfl_sync(0xffffffffu, x, 8), acc0);          \
        acc1 = fmaf((Ab)[2].y, __shfl_sync(0xffffffffu, x, 9), acc1);          \
        acc0 = fmaf((Ab)[2].z, __shfl_sync(0xffffffffu, x, 10), acc0);         \
        acc1 = fmaf((Ab)[2].w, __shfl_sync(0xffffffffu, x, 11), acc1);         \
        acc0 = fmaf((Ab)[3].x, __shfl_sync(0xffffffffu, x, 12), acc0);         \
        acc1 = fmaf((Ab)[3].y, __shfl_sync(0xffffffffu, x, 13), acc1);         \
        acc0 = fmaf((Ab)[3].z, __shfl_sync(0xffffffffu, x, 14), acc0);         \
        acc1 = fmaf((Ab)[3].w, __shfl_sync(0xffffffffu, x, 15), acc1);         \
        acc0 = fmaf((Ab)[4].x, (ob).x, acc0);                                  \
        acc1 = fmaf((Ab)[4].y, (ob).y, acc1);                                  \
        acc0 = fmaf((Ab)[4].z, (ob).z, acc0);                                  \
        acc1 = fmaf((Ab)[4].w, (ob).w, acc1);                                  \
        res = acc0 + acc1;                                                     \
        if (lane < 16) x = res;                                                \
        else if (lane < 20) op[((tt) + 1) * 4 + (lane - 16)] = res;            \
    } while (0)

__global__ __launch_bounds__(256, 1) void fused_kernel(
    const float* __restrict__ inp, float* __restrict__ out,
    const float* __restrict__ F, const float* __restrict__ H,
    const float* __restrict__ Q, const float* __restrict__ R,
    const float* __restrict__ x0, const float* __restrict__ sd)
{
    // producer shared state
    __shared__ float sP[16][ROWF];
    __shared__ float sT[16][ROWF];
    __shared__ float sA[16][ROWF];
    __shared__ float sF[16][ROWF];
    __shared__ float sQ[16][ROWF];
    __shared__ float sH[4][ROWF];
    __shared__ float sHP[4][ROWF];
    __shared__ float sHA[4][ROWF];
    __shared__ __align__(16) float sFHP[16][4];
    __shared__ __align__(16) float sL[16][4];
    __shared__ __align__(16) float sLR[16][4];
    __shared__ float sS[4][4], sSi[4][4], scof[4][4], sR[4][4], sHB[4][4];
    __shared__ float ssd2[16], ss0[16], srdet;
    // consumer staging buffers
    __shared__ __align__(16) float4 sbuf[CHF4];   // 24 KB
    __shared__ __align__(16) float4 sobs[8][16];  // 15 used per warp

    const int tid = threadIdx.x;

    if (blockIdx.x == 0) {
        // ============ PRODUCER: Joseph Riccati, 5 barriers/step ============
        const int i = tid >> 4, j = tid & 15;

        sF[i][j] = F[i * 16 + j];
        sQ[i][j] = Q[i * 16 + j];
        if (i < 4) sH[i][j] = H[i * 16 + j];
        if (tid < 16) {
            sR[tid >> 2][tid & 3] = R[tid];
            float v = sd[tid];
            ssd2[tid] = v * v;
        }
        __syncthreads();

        // P = F diag(sd^2) F^T + Q ; s0 = F x0 ; y0 = H s0
        {
            float a0 = sQ[i][j], a1 = 0.f, a2 = 0.f, a3 = 0.f;
#pragma unroll
            for (int k = 0; k < 16; k += 4) {
                a0 = fmaf(sF[i][k + 0] * ssd2[k + 0], sF[j][k + 0], a0);
                a1 = fmaf(sF[i][k + 1] * ssd2[k + 1], sF[j][k + 1], a1);
                a2 = fmaf(sF[i][k + 2] * ssd2[k + 2], sF[j][k + 2], a2);
                a3 = fmaf(sF[i][k + 3] * ssd2[k + 3], sF[j][k + 3], a3);
            }
            sP[i][j] = (a0 + a1) + (a2 + a3);
        }
        if (tid < 16) {
            float acc = 0.f;
#pragma unroll
            for (int k = 0; k < 16; k++) acc = fmaf(sF[tid][k], x0[k], acc);
            ss0[tid] = acc;
            g_s0[tid] = acc;
        }
        __syncthreads();
        if (tid < 4) {
            float acc = 0.f;
#pragma unroll
            for (int k = 0; k < 16; k++) acc = fmaf(sH[tid][k], ss0[k], acc);
            g_y0[tid] = acc;
        }

        float* blob = (float*)g_blob;
        const int c4 = j >> 2, w = j & 3;

#pragma unroll 1
        for (int t = 0; t < NSTEP; ++t) {
            float* base = blob + t * 400;

            // stage1: HP = H P (64 threads)
            if (tid < 64) {
                int m = tid >> 4, jj = tid & 15;
                float a0 = 0.f, a1 = 0.f, a2 = 0.f, a3 = 0.f;
#pragma unroll
                for (int k = 0; k < 16; k += 4) {
                    a0 = fmaf(sH[m][k + 0], sP[k + 0][jj], a0);
                    a1 = fmaf(sH[m][k + 1], sP[k + 1][jj], a1);
                    a2 = fmaf(sH[m][k + 2], sP[k + 2][jj], a2);
                    a3 = fmaf(sH[m][k + 3], sP[k + 3][jj], a3);
                }
                sHP[m][jj] = (a0 + a1) + (a2 + a3);
            }
            __syncthreads();   // bar1

            // stage2: warp0 (tid<16): S = HP H^T + R, cofactor inverse.
            //         threads 64..127: FHP[i][n] = sum_k F[i][k] * HP[n][k]
            if (tid < 16) {
                int m = tid >> 2, n = tid & 3;
                float s0 = sR[m][n], s1 = 0.f, s2 = 0.f, s3 = 0.f;
#pragma unroll
                for (int k = 0; k < 16; k += 4) {
                    s0 = fmaf(sHP[m][k + 0], sH[n][k + 0], s0);
                    s1 = fmaf(sHP[m][k + 1], sH[n][k + 1], s1);
                    s2 = fmaf(sHP[m][k + 2], sH[n][k + 2], s2);
                    s3 = fmaf(sHP[m][k + 3], sH[n][k + 3], s3);
                }
                sS[m][n] = (s0 + s1) + (s2 + s3);
                __syncwarp(0xffffu);
                int r0 = 0 + (0 >= m), r1 = 1 + (1 >= m), r2 = 2 + (2 >= m);
                int c0 = 0 + (0 >= n), c1 = 1 + (1 >= n), c2 = 2 + (2 >= n);
                float a = sS[r0][c0], b = sS[r0][c1], c = sS[r0][c2];
                float d = sS[r1][c0], e = sS[r1][c1], f = sS[r1][c2];
                float g = sS[r2][c0], h = sS[r2][c1], i2 = sS[r2][c2];
                float minor = a * (e * i2 - f * h) - b * (d * i2 - f * g) + c * (d * h - e * g);
                scof[m][n] = ((m + n) & 1) ? -minor : minor;
                __syncwarp(0xffffu);
                if (tid == 0) {
                    float det = sS[0][0] * scof[0][0] + sS[0][1] * scof[0][1] +
                                sS[0][2] * scof[0][2] + sS[0][3] * scof[0][3];
                    srdet = __fdividef(1.f, det);
                }
                __syncwarp(0xffffu);
                sSi[m][n] = scof[n][m] * srdet;   // Sinv = adj(S)/det
            }
            if (tid >= 64 && tid < 128) {
                int ii = (tid - 64) >> 2, n = (tid - 64) & 3;
                float a0 = 0.f, a1 = 0.f, a2 = 0.f, a3 = 0.f;
#pragma unroll
                for (int k = 0; k < 16; k += 4) {
                    a0 = fmaf(sF[ii][k + 0], sHP[n][k + 0], a0);
                    a1 = fmaf(sF[ii][k + 1], sHP[n][k + 1], a1);
                    a2 = fmaf(sF[ii][k + 2], sHP[n][k + 2], a2);
                    a3 = fmaf(sF[ii][k + 3], sHP[n][k + 3], a3);
                }
                sFHP[ii][n] = (a0 + a1) + (a2 + a3);
            }
            __syncthreads();   // bar2

            // stage3': merged. All threads: A[i][j] = F - FHP*(Si*H) (redundant SiH).
            //          tid 64..127: L = FHP*Si. tid 128..191: LR = FHP*(Si*R).
            //          Blob stores of A, L issue here (register-sourced).
            {
                float sih0, sih1, sih2, sih3;
                {
                    float hj0 = sH[0][j], hj1 = sH[1][j], hj2 = sH[2][j], hj3 = sH[3][j];
                    sih0 = sSi[0][0] * hj0;
                    sih1 = sSi[1][0] * hj0;
                    sih2 = sSi[2][0] * hj0;
                    sih3 = sSi[3][0] * hj0;
                    sih0 = fmaf(sSi[0][1], hj1, sih0);
                    sih1 = fmaf(sSi[1][1], hj1, sih1);
                    sih2 = fmaf(sSi[2][1], hj1, sih2);
                    sih3 = fmaf(sSi[3][1], hj1, sih3);
                    sih0 = fmaf(sSi[0][2], hj2, sih0);
                    sih1 = fmaf(sSi[1][2], hj2, sih1);
                    sih2 = fmaf(sSi[2][2], hj2, sih2);
                    sih3 = fmaf(sSi[3][2], hj2, sih3);
                    sih0 = fmaf(sSi[0][3], hj3, sih0);
                    sih1 = fmaf(sSi[1][3], hj3, sih1);
                    sih2 = fmaf(sSi[2][3], hj3, sih2);
                    sih3 = fmaf(sSi[3][3], hj3, sih3);
                }
                float a = sF[i][j];
                a = fmaf(-sFHP[i][0], sih0, a);
                a = fmaf(-sFHP[i][1], sih1, a);
                a = fmaf(-sFHP[i][2], sih2, a);
                a = fmaf(-sFHP[i][3], sih3, a);
                sA[i][j] = a;
                base[(c4 * 20 + i) * 4 + w] = a;
            }
            if (tid >= 64 && tid < 128) {
                int ii = (tid - 64) >> 2, m = (tid - 64) & 3;
                float acc = 0.f;
#pragma unroll
                for (int n = 0; n < 4; n++) acc = fmaf(sFHP[ii][n], sSi[n][m], acc);
                sL[ii][m] = acc;
                base[(4 * 20 + ii) * 4 + m] = acc;
            } else if (tid >= 128 && tid < 192) {
                int ii = (tid - 128) >> 2, m = (tid - 128) & 3;
                float sir0 = 0.f, sir1 = 0.f, sir2 = 0.f, sir3 = 0.f;
#pragma unroll
                for (int n = 0; n < 4; n++) {
                    float rn = sR[n][m];
                    sir0 = fmaf(sSi[0][n], rn, sir0);
                    sir1 = fmaf(sSi[1][n], rn, sir1);
                    sir2 = fmaf(sSi[2][n], rn, sir2);
                    sir3 = fmaf(sSi[3][n], rn, sir3);
                }
                float acc = sFHP[ii][0] * sir0;
                acc = fmaf(sFHP[ii][1], sir1, acc);
                acc = fmaf(sFHP[ii][2], sir2, acc);
                acc = fmaf(sFHP[ii][3], sir3, acc);
                sLR[ii][m] = acc;
            }
            __syncthreads();   // bar3

            // stage4': T = A P (all); HA = H A (tid<64); HB = H L (tid 64..79)
            {
                float a0 = 0.f, a1 = 0.f, a2 = 0.f, a3 = 0.f;
#pragma unroll
                for (int k = 0; k < 16; k += 4) {
                    a0 = fmaf(sA[i][k + 0], sP[k + 0][j], a0);
                    a1 = fmaf(sA[i][k + 1], sP[k + 1][j], a1);
                    a2 = fmaf(sA[i][k + 2], sP[k + 2][j], a2);
                    a3 = fmaf(sA[i][k + 3], sP[k + 3][j], a3);
                }
                sT[i][j] = (a0 + a1) + (a2 + a3);
            }
            if (tid < 64) {
                int m = tid >> 4, jj = tid & 15;
                float acc = 0.f;
#pragma unroll
                for (int k = 0; k < 16; k++) acc = fmaf(sH[m][k], sA[k][jj], acc);
                sHA[m][jj] = acc;
            } else if (tid < 80) {
                int m = (tid - 64) >> 2, n = (tid - 64) & 3;
                float acc = 0.f;
#pragma unroll
                for (int k = 0; k < 16; k++) acc = fmaf(sH[m][k], sL[k][n], acc);
                sHB[m][n] = acc;
            }
            __syncthreads();   // bar4

            // stage5': P' = T A^T + LR L^T + Q ; HA/HB blob ; convergence
            int flag;
            {
                float a0 = sQ[i][j], a1 = 0.f, a2 = 0.f, a3 = 0.f;
#pragma unroll
                for (int k = 0; k < 16; k += 4) {
                    a0 = fmaf(sT[i][k + 0], sA[j][k + 0], a0);
                    a1 = fmaf(sT[i][k + 1], sA[j][k + 1], a1);
                    a2 = fmaf(sT[i][k + 2], sA[j][k + 2], a2);
                    a3 = fmaf(sT[i][k + 3], sA[j][k + 3], a3);
                }
                float acc = (a0 + a1) + (a2 + a3);
#pragma unroll
                for (int m = 0; m < 4; m++) acc = fmaf(sLR[i][m], sL[j][m], acc);
                if (i < 4) base[(c4 * 20 + 16 + i) * 4 + w] = sHA[i][j];
                if (i < 4 && j < 4) base[(4 * 20 + 16 + i) * 4 + j] = sHB[i][j];
                float oldp = sP[i][j];
                // NaN-safe (NaN -> flag=1)
                flag = !(fabsf(acc - oldp) <= 5e-4f * fabsf(acc) + 5e-5f);
                sP[i][j] = acc;
            }
            if (!__syncthreads_or(flag)) {   // bar5 (loop barrier)
                // converged: replicate fixed-point map for remaining steps
                for (int t2 = t + 1; t2 < NSTEP; ++t2) {
                    float* b2 = blob + t2 * 400;
                    b2[(c4 * 20 + i) * 4 + w] = sA[i][j];
                    if (j < 4) b2[(4 * 20 + i) * 4 + j] = sL[i][j];
                    if (i < 4) b2[(c4 * 20 + 16 + i) * 4 + w] = sHA[i][j];
                    if (i < 4 && j < 4) b2[(4 * 20 + 16 + i) * 4 + j] = sHB[i][j];
                }
                __syncthreads();
                if (tid == 0) {
                    __threadfence();
                    *(volatile int*)&g_ready = NCHUNK;
                }
                return;
            }
            if (((t + 1) % CH) == 0) {
                if (tid == 0) {
                    __threadfence();
                    *(volatile int*)&g_ready = (t + 1) / CH;
                }
            }
        }
        return;
    }

    // ==================== CONSUMERS: warp-per-batch scan =====================
    const int lane = tid & 31;
    const int wrp = tid >> 5;
    const int b = ((blockIdx.x - 1) << 3) + wrp;
    const int g = (lane < 20) ? lane : 0;

    // wait for chunk 0 (also guarantees g_s0/g_y0 visible)
    if (tid == 0) {
        while (*(volatile int*)&g_ready < 1) __nanosleep(200);
        __threadfence();
    }
    __syncthreads();

    float x = (lane < 16) ? g_s0[lane] : 0.f;
    float* op = out + b * (NT * NM);
    if (lane >= 16 && lane < 20) op[lane - 16] = g_y0[lane - 16];

    const float4* gb = g_blob;
    const int bb = (blockIdx.x - 1) << 3;

#pragma unroll 1
    for (int c = 0; c < NCHUNK; ++c) {
        if (c > 0) {
            if (tid == 0) {
                while (*(volatile int*)&g_ready < c + 1) __nanosleep(200);
                __threadfence();
            }
            __syncthreads();
        }
        // stage chunk c blob + this block's obs into shared
#pragma unroll
        for (int r = 0; r < 6; r++) {
            int idx = tid + r * 256;
            if (idx < CHF4) sbuf[idx] = gb[c * CHF4 + idx];
        }
        if (tid < 8 * CH) {
            int w2 = tid / CH, s = tid - w2 * CH;
            int tt = c * CH + s;   // <= 254
            sobs[w2][s] = *(const float4*)(inp + ((bb + w2) * NT + tt) * 4);
        }
        __syncthreads();

        const float4* s4 = sbuf;
        int t = c * CH;
#pragma unroll 1
        for (int s = 0; s < CH; ++s, ++t) {
            float4 A[5];
#pragma unroll
            for (int cc = 0; cc < 5; cc++) A[cc] = s4[s * 100 + cc * 20 + g];
            float4 ob = sobs[wrp][s];
            KF_STEP(A, ob, t);
        }
        __syncthreads();  // all readers done before next chunk overwrites
    }
}

extern "C" void kernel_launch(void* const* d_in, const int* in_sizes, int n_in,
                              void* d_out, int out_size) {
    const float* inp = (const float*)d_in[0];
    const float* F   = (const float*)d_in[1];
    const float* H   = (const float*)d_in[2];
    const float* Q   = (const float*)d_in[3];
    const float* R   = (const float*)d_in[4];
    const float* x0  = (const float*)d_in[5];
    const float* sd  = (const float*)d_in[6];
    float* out = (float*)d_out;

    reset_kernel<<<1, 1>>>();
    fused_kernel<<<129, 256>>>(inp, out, F, H, Q, R, x0, sd);
}

// round 11
// speedup vs baseline: 1.5332x; 1.0572x over previous
#include <cuda_runtime.h>

#define NB 1024
#define NT 256
#define NS 16
#define NM 4
#define NSTEP 255
#define ROWF 20
#define CH 15            // chunk: 255 = 17 * 15
#define NCHUNK 17
#define CHF4 (CH * 100)  // float4 per chunk = 1500

// blob[t]: 100 float4 per step, float4-column-major:
//   f4 index (c*20 + row): row<16 state rows, row 16+m measurement rows.
//   Column block c<4 covers matrix cols 4c..4c+3; c==4 covers cols 16..19 (L/HB).
__device__ float4 g_blob[NSTEP * 100];
__device__ float  g_s0[16];
__device__ float  g_y0[4];
__device__ int    g_ready;   // chunks published (monotonic within a launch)

__global__ void reset_kernel() { g_ready = 0; }

// ---------------------------------------------------------------------------
// KF consumer step: lanes 0..15 new state, lanes 16..19 write output.
// ---------------------------------------------------------------------------
#define KF_STEP(Ab, ob, tt)                                                    \
    do {                                                                       \
        float acc0, acc1, res;                                                 \
        acc0 = (Ab)[0].x * __shfl_sync(0xffffffffu, x, 0);                     \
        acc1 = (Ab)[0].y * __shfl_sync(0xffffffffu, x, 1);                     \
        acc0 = fmaf((Ab)[0].z, __shfl_sync(0xffffffffu, x, 2), acc0);          \
        acc1 = fmaf((Ab)[0].w, __shfl_sync(0xffffffffu, x, 3), acc1);          \
        acc0 = fmaf((Ab)[1].x, __shfl_sync(0xffffffffu, x, 4), acc0);          \
        acc1 = fmaf((Ab)[1].y, __shfl_sync(0xffffffffu, x, 5), acc1);          \
        acc0 = fmaf((Ab)[1].z, __shfl_sync(0xffffffffu, x, 6), acc0);          \
        acc1 = fmaf((Ab)[1].w, __shfl_sync(0xffffffffu, x, 7), acc1);          \
        acc0 = fmaf((Ab)[2].x, __shfl_sync(0xffffffffu, x, 8), acc0);          \
        acc1 = fmaf((Ab)[2].y, __shfl_sync(0xffffffffu, x, 9), acc1);          \
        acc0 = fmaf((Ab)[2].z, __shfl_sync(0xffffffffu, x, 10), acc0);         \
        acc1 = fmaf((Ab)[2].w, __shfl_sync(0xffffffffu, x, 11), acc1);         \
        acc0 = fmaf((Ab)[3].x, __shfl_sync(0xffffffffu, x, 12), acc0);         \
        acc1 = fmaf((Ab)[3].y, __shfl_sync(0xffffffffu, x, 13), acc1);         \
        acc0 = fmaf((Ab)[3].z, __shfl_sync(0xffffffffu, x, 14), acc0);         \
        acc1 = fmaf((Ab)[3].w, __shfl_sync(0xffffffffu, x, 15), acc1);         \
        acc0 = fmaf((Ab)[4].x, (ob).x, acc0);                                  \
        acc1 = fmaf((Ab)[4].y, (ob).y, acc1);                                  \
        acc0 = fmaf((Ab)[4].z, (ob).z, acc0);                                  \
        acc1 = fmaf((Ab)[4].w, (ob).w, acc1);                                  \
        res = acc0 + acc1;                                                     \
        if (lane < 16) x = res;                                                \
        else if (lane < 20) op[((tt) + 1) * 4 + (lane - 16)] = res;            \
    } while (0)

__global__ __launch_bounds__(256, 1) void fused_kernel(
    const float* __restrict__ inp, float* __restrict__ out,
    const float* __restrict__ F, const float* __restrict__ H,
    const float* __restrict__ Q, const float* __restrict__ R,
    const float* __restrict__ x0, const float* __restrict__ sd)
{
    // producer shared state (P double-buffered)
    __shared__ float sPb[2][16][ROWF];
    __shared__ float sA[16][ROWF];
    __shared__ float sF[16][ROWF];
    __shared__ float sQ[16][ROWF];
    __shared__ float sH[4][ROWF];
    __shared__ float sHP[4][ROWF];
    __shared__ float sHA[4][ROWF];
    __shared__ __align__(16) float sFHP[16][4];
    __shared__ __align__(16) float sL[16][4];
    __shared__ __align__(16) float sLR[16][4];
    __shared__ float sS[4][4], sSi[4][4], scof[4][4], sR[4][4], sHB[4][4];
    __shared__ float ssd2[16], ss0[16], srdet;
    // consumer staging buffers
    __shared__ __align__(16) float4 sbuf[CHF4];   // 24 KB
    __shared__ __align__(16) float4 sobs[8][16];  // 15 used per warp

    const int tid = threadIdx.x;

    if (blockIdx.x == 0) {
        // ============ PRODUCER: Joseph Riccati, 4 barriers/step ============
        const int i = tid >> 4, j = tid & 15;
        const int l = tid & 31;
        const int half = l & 16;   // shfl half-select for row-pair warps

        sF[i][j] = F[i * 16 + j];
        sQ[i][j] = Q[i * 16 + j];
        if (i < 4) sH[i][j] = H[i * 16 + j];
        if (tid < 16) {
            sR[tid >> 2][tid & 3] = R[tid];
            float v = sd[tid];
            ssd2[tid] = v * v;
        }
        __syncthreads();

        // P0 = F diag(sd^2) F^T + Q ; s0 = F x0 ; y0 = H s0
        {
            float a0 = sQ[i][j], a1 = 0.f, a2 = 0.f, a3 = 0.f;
#pragma unroll
            for (int k = 0; k < 16; k += 4) {
                a0 = fmaf(sF[i][k + 0] * ssd2[k + 0], sF[j][k + 0], a0);
                a1 = fmaf(sF[i][k + 1] * ssd2[k + 1], sF[j][k + 1], a1);
                a2 = fmaf(sF[i][k + 2] * ssd2[k + 2], sF[j][k + 2], a2);
                a3 = fmaf(sF[i][k + 3] * ssd2[k + 3], sF[j][k + 3], a3);
            }
            sPb[0][i][j] = (a0 + a1) + (a2 + a3);
        }
        if (tid < 16) {
            float acc = 0.f;
#pragma unroll
            for (int k = 0; k < 16; k++) acc = fmaf(sF[tid][k], x0[k], acc);
            ss0[tid] = acc;
            g_s0[tid] = acc;
        }
        __syncthreads();
        if (tid < 4) {
            float acc = 0.f;
#pragma unroll
            for (int k = 0; k < 16; k++) acc = fmaf(sH[tid][k], ss0[k], acc);
            g_y0[tid] = acc;
        }

        float* blob = (float*)g_blob;
        const int c4 = j >> 2, w = j & 3;

#pragma unroll 1
        for (int t = 0; t < NSTEP; ++t) {
            float* base = blob + t * 400;
            float (*cur)[ROWF] = sPb[t & 1];
            float (*nxt)[ROWF] = sPb[(t + 1) & 1];

            // stage1: HP = H P (64 threads)
            if (tid < 64) {
                int m = tid >> 4, jj = tid & 15;
                float a0 = 0.f, a1 = 0.f, a2 = 0.f, a3 = 0.f;
#pragma unroll
                for (int k = 0; k < 16; k += 4) {
                    a0 = fmaf(sH[m][k + 0], cur[k + 0][jj], a0);
                    a1 = fmaf(sH[m][k + 1], cur[k + 1][jj], a1);
                    a2 = fmaf(sH[m][k + 2], cur[k + 2][jj], a2);
                    a3 = fmaf(sH[m][k + 3], cur[k + 3][jj], a3);
                }
                sHP[m][jj] = (a0 + a1) + (a2 + a3);
            }
            __syncthreads();   // bar1

            // stage2: warp0 (tid<16): S = HP H^T + R, cofactor inverse.
            //         threads 64..127: FHP[i][n] = sum_k F[i][k] * HP[n][k]
            if (tid < 16) {
                int m = tid >> 2, n = tid & 3;
                float s0 = sR[m][n], s1 = 0.f, s2 = 0.f, s3 = 0.f;
#pragma unroll
                for (int k = 0; k < 16; k += 4) {
                    s0 = fmaf(sHP[m][k + 0], sH[n][k + 0], s0);
                    s1 = fmaf(sHP[m][k + 1], sH[n][k + 1], s1);
                    s2 = fmaf(sHP[m][k + 2], sH[n][k + 2], s2);
                    s3 = fmaf(sHP[m][k + 3], sH[n][k + 3], s3);
                }
                sS[m][n] = (s0 + s1) + (s2 + s3);
                __syncwarp(0xffffu);
                int r0 = 0 + (0 >= m), r1 = 1 + (1 >= m), r2 = 2 + (2 >= m);
                int c0 = 0 + (0 >= n), c1 = 1 + (1 >= n), c2 = 2 + (2 >= n);
                float a = sS[r0][c0], b = sS[r0][c1], c = sS[r0][c2];
                float d = sS[r1][c0], e = sS[r1][c1], f = sS[r1][c2];
                float g = sS[r2][c0], h = sS[r2][c1], i2 = sS[r2][c2];
                float minor = a * (e * i2 - f * h) - b * (d * i2 - f * g) + c * (d * h - e * g);
                scof[m][n] = ((m + n) & 1) ? -minor : minor;
                __syncwarp(0xffffu);
                if (tid == 0) {
                    float det = sS[0][0] * scof[0][0] + sS[0][1] * scof[0][1] +
                                sS[0][2] * scof[0][2] + sS[0][3] * scof[0][3];
                    srdet = __fdividef(1.f, det);
                }
                __syncwarp(0xffffu);
                sSi[m][n] = scof[n][m] * srdet;   // Sinv = adj(S)/det
            }
            if (tid >= 64 && tid < 128) {
                int ii = (tid - 64) >> 2, n = (tid - 64) & 3;
                float a0 = 0.f, a1 = 0.f, a2 = 0.f, a3 = 0.f;
#pragma unroll
                for (int k = 0; k < 16; k += 4) {
                    a0 = fmaf(sF[ii][k + 0], sHP[n][k + 0], a0);
                    a1 = fmaf(sF[ii][k + 1], sHP[n][k + 1], a1);
                    a2 = fmaf(sF[ii][k + 2], sHP[n][k + 2], a2);
                    a3 = fmaf(sF[ii][k + 3], sHP[n][k + 3], a3);
                }
                sFHP[ii][n] = (a0 + a1) + (a2 + a3);
            }
            __syncthreads();   // bar2

            // stage3': A = F - FHP*(Si*H) (all, redundant SiH, result kept in reg).
            //          tid 64..127: L = FHP*Si. tid 128..191: LR = FHP*(Si*R).
            float areg;
            {
                float sih0, sih1, sih2, sih3;
                {
                    float hj0 = sH[0][j], hj1 = sH[1][j], hj2 = sH[2][j], hj3 = sH[3][j];
                    sih0 = sSi[0][0] * hj0;
                    sih1 = sSi[1][0] * hj0;
                    sih2 = sSi[2][0] * hj0;
                    sih3 = sSi[3][0] * hj0;
                    sih0 = fmaf(sSi[0][1], hj1, sih0);
                    sih1 = fmaf(sSi[1][1], hj1, sih1);
                    sih2 = fmaf(sSi[2][1], hj1, sih2);
                    sih3 = fmaf(sSi[3][1], hj1, sih3);
                    sih0 = fmaf(sSi[0][2], hj2, sih0);
                    sih1 = fmaf(sSi[1][2], hj2, sih1);
                    sih2 = fmaf(sSi[2][2], hj2, sih2);
                    sih3 = fmaf(sSi[3][2], hj2, sih3);
                    sih0 = fmaf(sSi[0][3], hj3, sih0);
                    sih1 = fmaf(sSi[1][3], hj3, sih1);
                    sih2 = fmaf(sSi[2][3], hj3, sih2);
                    sih3 = fmaf(sSi[3][3], hj3, sih3);
                }
                float a = sF[i][j];
                a = fmaf(-sFHP[i][0], sih0, a);
                a = fmaf(-sFHP[i][1], sih1, a);
                a = fmaf(-sFHP[i][2], sih2, a);
                a = fmaf(-sFHP[i][3], sih3, a);
                areg = a;
                sA[i][j] = a;
                base[(c4 * 20 + i) * 4 + w] = a;
            }
            if (tid >= 64 && tid < 128) {
                int ii = (tid - 64) >> 2, m = (tid - 64) & 3;
                float acc = 0.f;
#pragma unroll
                for (int n = 0; n < 4; n++) acc = fmaf(sFHP[ii][n], sSi[n][m], acc);
                sL[ii][m] = acc;
                base[(4 * 20 + ii) * 4 + m] = acc;
            } else if (tid >= 128 && tid < 192) {
                int ii = (tid - 128) >> 2, m = (tid - 128) & 3;
                float sir0 = 0.f, sir1 = 0.f, sir2 = 0.f, sir3 = 0.f;
#pragma unroll
                for (int n = 0; n < 4; n++) {
                    float rn = sR[n][m];
                    sir0 = fmaf(sSi[0][n], rn, sir0);
                    sir1 = fmaf(sSi[1][n], rn, sir1);
                    sir2 = fmaf(sSi[2][n], rn, sir2);
                    sir3 = fmaf(sSi[3][n], rn, sir3);
                }
                float acc = sFHP[ii][0] * sir0;
                acc = fmaf(sFHP[ii][1], sir1, acc);
                acc = fmaf(sFHP[ii][2], sir2, acc);
                acc = fmaf(sFHP[ii][3], sir3, acc);
                sLR[ii][m] = acc;
            }
            __syncthreads();   // bar3

            // fused stage4+5 (no intermediate barrier; P double-buffered):
            //   T[i][j] = sum_k A[i][k] P[k][j]   (A row via shfl, T in reg)
            //   HA on warps 6-7, HB on tid 176..191
            //   P'[i][j] = sum_k T[i][k] A[j][k] + sum_m LR[i][m] L[j][m] + Q
            float treg;
            {
                float t0 = 0.f, t1 = 0.f, t2 = 0.f, t3 = 0.f;
#pragma unroll
                for (int k = 0; k < 16; k += 4) {
                    t0 = fmaf(__shfl_sync(0xffffffffu, areg, half | (k + 0)), cur[k + 0][j], t0);
                    t1 = fmaf(__shfl_sync(0xffffffffu, areg, half | (k + 1)), cur[k + 1][j], t1);
                    t2 = fmaf(__shfl_sync(0xffffffffu, areg, half | (k + 2)), cur[k + 2][j], t2);
                    t3 = fmaf(__shfl_sync(0xffffffffu, areg, half | (k + 3)), cur[k + 3][j], t3);
                }
                treg = (t0 + t1) + (t2 + t3);
            }
            if (tid >= 192) {
                int m = (tid - 192) >> 4, jj = tid & 15;
                float acc = 0.f;
#pragma unroll
                for (int k = 0; k < 16; k++) acc = fmaf(sH[m][k], sA[k][jj], acc);
                sHA[m][jj] = acc;
                base[((jj >> 2) * 20 + 16 + m) * 4 + (jj & 3)] = acc;
            } else if (tid >= 176) {
                int m = (tid - 176) >> 2, n = (tid - 176) & 3;
                float acc = 0.f;
#pragma unroll
                for (int k = 0; k < 16; k++) acc = fmaf(sH[m][k], sL[k][n], acc);
                sHB[m][n] = acc;
                base[(4 * 20 + 16 + m) * 4 + n] = acc;
            }
            int flag;
            {
                float a0 = sQ[i][j], a1 = 0.f, a2 = 0.f, a3 = 0.f;
#pragma unroll
                for (int k = 0; k < 16; k += 4) {
                    a0 = fmaf(__shfl_sync(0xffffffffu, treg, half | (k + 0)), sA[j][k + 0], a0);
                    a1 = fmaf(__shfl_sync(0xffffffffu, treg, half | (k + 1)), sA[j][k + 1], a1);
                    a2 = fmaf(__shfl_sync(0xffffffffu, treg, half | (k + 2)), sA[j][k + 2], a2);
                    a3 = fmaf(__shfl_sync(0xffffffffu, treg, half | (k + 3)), sA[j][k + 3], a3);
                }
                float acc = (a0 + a1) + (a2 + a3);
#pragma unroll
                for (int m = 0; m < 4; m++) acc = fmaf(sLR[i][m], sL[j][m], acc);
                float oldp = cur[i][j];
                // NaN-safe (NaN -> flag=1)
                flag = !(fabsf(acc - oldp) <= 1e-3f * fabsf(acc) + 1e-4f);
                nxt[i][j] = acc;
            }
            if (!__syncthreads_or(flag)) {   // bar4 (loop barrier)
                // converged: replicate fixed-point map for remaining steps
                for (int t2 = t + 1; t2 < NSTEP; ++t2) {
                    float* b2 = blob + t2 * 400;
                    b2[(c4 * 20 + i) * 4 + w] = sA[i][j];
                    if (j < 4) b2[(4 * 20 + i) * 4 + j] = sL[i][j];
                    if (i < 4) b2[(c4 * 20 + 16 + i) * 4 + w] = sHA[i][j];
                    if (i < 4 && j < 4) b2[(4 * 20 + 16 + i) * 4 + j] = sHB[i][j];
                }
                __syncthreads();
                if (tid == 0) {
                    __threadfence();
                    *(volatile int*)&g_ready = NCHUNK;
                }
                return;
            }
            if (((t + 1) % CH) == 0) {
                if (tid == 0) {
                    __threadfence();
                    *(volatile int*)&g_ready = (t + 1) / CH;
                }
            }
        }
        return;
    }

    // ==================== CONSUMERS: warp-per-batch scan =====================
    const int lane = tid & 31;
    const int wrp = tid >> 5;
    const int b = ((blockIdx.x - 1) << 3) + wrp;
    const int g = (lane < 20) ? lane : 0;

    // wait for chunk 0 (also guarantees g_s0/g_y0 visible)
    if (tid == 0) {
        while (*(volatile int*)&g_ready < 1) __nanosleep(200);
        __threadfence();
    }
    __syncthreads();

    float x = (lane < 16) ? g_s0[lane] : 0.f;
    float* op = out + b * (NT * NM);
    if (lane >= 16 && lane < 20) op[lane - 16] = g_y0[lane - 16];

    const float4* gb = g_blob;
    const int bb = (blockIdx.x - 1) << 3;

#pragma unroll 1
    for (int c = 0; c < NCHUNK; ++c) {
        if (c > 0) {
            if (tid == 0) {
                while (*(volatile int*)&g_ready < c + 1) __nanosleep(200);
                __threadfence();
            }
            __syncthreads();
        }
        // stage chunk c blob + this block's obs into shared
#pragma unroll
        for (int r = 0; r < 6; r++) {
            int idx = tid + r * 256;
            if (idx < CHF4) sbuf[idx] = gb[c * CHF4 + idx];
        }
        if (tid < 8 * CH) {
            int w2 = tid / CH, s = tid - w2 * CH;
            int tt = c * CH + s;   // <= 254
            sobs[w2][s] = *(const float4*)(inp + ((bb + w2) * NT + tt) * 4);
        }
        __syncthreads();

        const float4* s4 = sbuf;
        int t = c * CH;
#pragma unroll 1
        for (int s = 0; s < CH; ++s, ++t) {
            float4 A[5];
#pragma unroll
            for (int cc = 0; cc < 5; cc++) A[cc] = s4[s * 100 + cc * 20 + g];
            float4 ob = sobs[wrp][s];
            KF_STEP(A, ob, t);
        }
        __syncthreads();  // all readers done before next chunk overwrites
    }
}

extern "C" void kernel_launch(void* const* d_in, const int* in_sizes, int n_in,
                              void* d_out, int out_size) {
    const float* inp = (const float*)d_in[0];
    const float* F   = (const float*)d_in[1];
    const float* H   = (const float*)d_in[2];
    const float* Q   = (const float*)d_in[3];
    const float* R   = (const float*)d_in[4];
    const float* x0  = (const float*)d_in[5];
    const float* sd  = (const float*)d_in[6];
    float* out = (float*)d_out;

    reset_kernel<<<1, 1>>>();
    fused_kernel<<<129, 256>>>(inp, out, F, H, Q, R, x0, sd);
}

// round 12
// speedup vs baseline: 1.6922x; 1.1038x over previous
#include <cuda_runtime.h>

#define NB 1024
#define NT 256
#define NS 16
#define NM 4
#define NSTEP 255
#define ROWF 20
#define CH 15            // chunk: 255 = 17 * 15
#define NCHUNK 17
#define CHF4 (CH * 100)  // float4 per chunk = 1500

// blob[t]: 100 float4 per step, float4-column-major:
//   f4 index (c*20 + row): row<16 state rows, row 16+m measurement rows.
//   Column block c<4 covers matrix cols 4c..4c+3; c==4 covers cols 16..19 (L/HB).
__device__ float4 g_blob[NSTEP * 100];
__device__ float  g_s0[16];
__device__ float  g_y0[4];
__device__ int    g_ready;   // chunks published (monotonic within a launch)

__global__ void reset_kernel() { g_ready = 0; }

// ---------------------------------------------------------------------------
// KF consumer step: lanes 0..15 new state, lanes 16..19 write output.
// ---------------------------------------------------------------------------
#define KF_STEP(Ab, ob, tt)                                                    \
    do {                                                                       \
        float acc0, acc1, res;                                                 \
        acc0 = (Ab)[0].x * __shfl_sync(0xffffffffu, x, 0);                     \
        acc1 = (Ab)[0].y * __shfl_sync(0xffffffffu, x, 1);                     \
        acc0 = fmaf((Ab)[0].z, __shfl_sync(0xffffffffu, x, 2), acc0);          \
        acc1 = fmaf((Ab)[0].w, __shfl_sync(0xffffffffu, x, 3), acc1);          \
        acc0 = fmaf((Ab)[1].x, __shfl_sync(0xffffffffu, x, 4), acc0);          \
        acc1 = fmaf((Ab)[1].y, __shfl_sync(0xffffffffu, x, 5), acc1);          \
        acc0 = fmaf((Ab)[1].z, __shfl_sync(0xffffffffu, x, 6), acc0);          \
        acc1 = fmaf((Ab)[1].w, __shfl_sync(0xffffffffu, x, 7), acc1);          \
        acc0 = fmaf((Ab)[2].x, __shfl_sync(0xffffffffu, x, 8), acc0);          \
        acc1 = fmaf((Ab)[2].y, __shfl_sync(0xffffffffu, x, 9), acc1);          \
        acc0 = fmaf((Ab)[2].z, __shfl_sync(0xffffffffu, x, 10), acc0);         \
        acc1 = fmaf((Ab)[2].w, __shfl_sync(0xffffffffu, x, 11), acc1);         \
        acc0 = fmaf((Ab)[3].x, __shfl_sync(0xffffffffu, x, 12), acc0);         \
        acc1 = fmaf((Ab)[3].y, __shfl_sync(0xffffffffu, x, 13), acc1);         \
        acc0 = fmaf((Ab)[3].z, __shfl_sync(0xffffffffu, x, 14), acc0);         \
        acc1 = fmaf((Ab)[3].w, __shfl_sync(0xffffffffu, x, 15), acc1);         \
        acc0 = fmaf((Ab)[4].x, (ob).x, acc0);                                  \
        acc1 = fmaf((Ab)[4].y, (ob).y, acc1);                                  \
        acc0 = fmaf((Ab)[4].z, (ob).z, acc0);                                  \
        acc1 = fmaf((Ab)[4].w, (ob).w, acc1);                                  \
        res = acc0 + acc1;                                                     \
        if (lane < 16) x = res;                                                \
        else if (lane < 20) op[((tt) + 1) * 4 + (lane - 16)] = res;            \
    } while (0)

__global__ __launch_bounds__(256, 1) void fused_kernel(
    const float* __restrict__ inp, float* __restrict__ out,
    const float* __restrict__ F, const float* __restrict__ H,
    const float* __restrict__ Q, const float* __restrict__ R,
    const float* __restrict__ x0, const float* __restrict__ sd)
{
    // producer shared state (P double-buffered)
    __shared__ float sPb[2][16][ROWF];
    __shared__ float sA[16][ROWF];
    __shared__ float sF[16][ROWF];
    __shared__ float sQ[16][ROWF];
    __shared__ float sH[4][ROWF];
    __shared__ float sHP[4][ROWF];
    __shared__ float sHA[4][ROWF];
    __shared__ __align__(16) float sFHP[16][4];
    __shared__ __align__(16) float sL[16][4];
    __shared__ __align__(16) float sLR[16][4];
    __shared__ float sSi[4][4], sR[4][4], sHB[4][4];
    __shared__ float ssd2[16], ss0[16];
    // consumer staging buffers
    __shared__ __align__(16) float4 sbuf[CHF4];   // 24 KB
    __shared__ __align__(16) float4 sobs[8][16];  // 15 used per warp

    const int tid = threadIdx.x;

    if (blockIdx.x == 0) {
        // ============ PRODUCER: Joseph Riccati, 4 barriers/step ============
        const int i = tid >> 4, j = tid & 15;
        const int l = tid & 31;
        const int half = l & 16;   // shfl half-select for row-pair warps

        sF[i][j] = F[i * 16 + j];
        sQ[i][j] = Q[i * 16 + j];
        if (i < 4) sH[i][j] = H[i * 16 + j];
        if (tid < 16) {
            sR[tid >> 2][tid & 3] = R[tid];
            float v = sd[tid];
            ssd2[tid] = v * v;
        }
        __syncthreads();

        // P0 = F diag(sd^2) F^T + Q ; s0 = F x0 ; y0 = H s0
        {
            float a0 = sQ[i][j], a1 = 0.f, a2 = 0.f, a3 = 0.f;
#pragma unroll
            for (int k = 0; k < 16; k += 4) {
                a0 = fmaf(sF[i][k + 0] * ssd2[k + 0], sF[j][k + 0], a0);
                a1 = fmaf(sF[i][k + 1] * ssd2[k + 1], sF[j][k + 1], a1);
                a2 = fmaf(sF[i][k + 2] * ssd2[k + 2], sF[j][k + 2], a2);
                a3 = fmaf(sF[i][k + 3] * ssd2[k + 3], sF[j][k + 3], a3);
            }
            sPb[0][i][j] = (a0 + a1) + (a2 + a3);
        }
        if (tid < 16) {
            float acc = 0.f;
#pragma unroll
            for (int k = 0; k < 16; k++) acc = fmaf(sF[tid][k], x0[k], acc);
            ss0[tid] = acc;
            g_s0[tid] = acc;
        }
        __syncthreads();
        if (tid < 4) {
            float acc = 0.f;
#pragma unroll
            for (int k = 0; k < 16; k++) acc = fmaf(sH[tid][k], ss0[k], acc);
            g_y0[tid] = acc;
        }

        float* blob = (float*)g_blob;
        const int c4 = j >> 2, w = j & 3;

#pragma unroll 1
        for (int t = 0; t < NSTEP; ++t) {
            float* base = blob + t * 400;
            float (*cur)[ROWF] = sPb[t & 1];
            float (*nxt)[ROWF] = sPb[(t + 1) & 1];

            // stage1: HP = H P (64 threads)
            if (tid < 64) {
                int m = tid >> 4, jj = tid & 15;
                float a0 = 0.f, a1 = 0.f, a2 = 0.f, a3 = 0.f;
#pragma unroll
                for (int k = 0; k < 16; k += 4) {
                    a0 = fmaf(sH[m][k + 0], cur[k + 0][jj], a0);
                    a1 = fmaf(sH[m][k + 1], cur[k + 1][jj], a1);
                    a2 = fmaf(sH[m][k + 2], cur[k + 2][jj], a2);
                    a3 = fmaf(sH[m][k + 3], cur[k + 3][jj], a3);
                }
                sHP[m][jj] = (a0 + a1) + (a2 + a3);
            }
            __syncthreads();   // bar1

            // stage2: warp0 (tid<16): S = HP H^T + R and all-shfl 4x4 inverse.
            //         threads 64..127: FHP[i][n] = sum_k F[i][k] * HP[n][k]
            if (tid < 16) {
                int m = tid >> 2, n = tid & 3;
                float s0 = sR[m][n], s1 = 0.f, s2 = 0.f, s3 = 0.f;
#pragma unroll
                for (int k = 0; k < 16; k += 4) {
                    s0 = fmaf(sHP[m][k + 0], sH[n][k + 0], s0);
                    s1 = fmaf(sHP[m][k + 1], sH[n][k + 1], s1);
                    s2 = fmaf(sHP[m][k + 2], sH[n][k + 2], s2);
                    s3 = fmaf(sHP[m][k + 3], sH[n][k + 3], s3);
                }
                float sv = (s0 + s1) + (s2 + s3);   // S[m][n], register only
                // cofactor via 9 shfls (lane r*4+c holds S[r][c])
                int r0 = 0 + (0 >= m), r1 = 1 + (1 >= m), r2 = 2 + (2 >= m);
                int cc0 = 0 + (0 >= n), cc1 = 1 + (1 >= n), cc2 = 2 + (2 >= n);
                float a = __shfl_sync(0xffffu, sv, r0 * 4 + cc0);
                float b = __shfl_sync(0xffffu, sv, r0 * 4 + cc1);
                float c = __shfl_sync(0xffffu, sv, r0 * 4 + cc2);
                float d = __shfl_sync(0xffffu, sv, r1 * 4 + cc0);
                float e = __shfl_sync(0xffffu, sv, r1 * 4 + cc1);
                float f = __shfl_sync(0xffffu, sv, r1 * 4 + cc2);
                float g = __shfl_sync(0xffffu, sv, r2 * 4 + cc0);
                float h = __shfl_sync(0xffffu, sv, r2 * 4 + cc1);
                float i2 = __shfl_sync(0xffffu, sv, r2 * 4 + cc2);
                float minor = a * (e * i2 - f * h) - b * (d * i2 - f * g) + c * (d * h - e * g);
                float cof = ((m + n) & 1) ? -minor : minor;
                // det: lanes 0..3 (m==0) butterfly-reduce sv*cof over n
                float dv = sv * cof;
                dv += __shfl_xor_sync(0xffffu, dv, 1);
                dv += __shfl_xor_sync(0xffffu, dv, 2);
                // transpose cofactor (independent of det chain)
                float cofT = __shfl_sync(0xffffu, cof, n * 4 + m);
                float rdet = __fdividef(1.f, dv);
                rdet = __shfl_sync(0xffffu, rdet, 0);
                sSi[m][n] = cofT * rdet;   // Sinv = adj(S)/det
            }
            if (tid >= 64 && tid < 128) {
                int ii = (tid - 64) >> 2, n = (tid - 64) & 3;
                float a0 = 0.f, a1 = 0.f, a2 = 0.f, a3 = 0.f;
#pragma unroll
                for (int k = 0; k < 16; k += 4) {
                    a0 = fmaf(sF[ii][k + 0], sHP[n][k + 0], a0);
                    a1 = fmaf(sF[ii][k + 1], sHP[n][k + 1], a1);
                    a2 = fmaf(sF[ii][k + 2], sHP[n][k + 2], a2);
                    a3 = fmaf(sF[ii][k + 3], sHP[n][k + 3], a3);
                }
                sFHP[ii][n] = (a0 + a1) + (a2 + a3);
            }
            __syncthreads();   // bar2

            // stage3': A = F - FHP*(Si*H) (all, redundant SiH, result kept in reg).
            //          tid 64..127: L = FHP*Si. tid 128..191: LR = FHP*(Si*R).
            float areg;
            {
                float sih0, sih1, sih2, sih3;
                {
                    float hj0 = sH[0][j], hj1 = sH[1][j], hj2 = sH[2][j], hj3 = sH[3][j];
                    sih0 = sSi[0][0] * hj0;
                    sih1 = sSi[1][0] * hj0;
                    sih2 = sSi[2][0] * hj0;
                    sih3 = sSi[3][0] * hj0;
                    sih0 = fmaf(sSi[0][1], hj1, sih0);
                    sih1 = fmaf(sSi[1][1], hj1, sih1);
                    sih2 = fmaf(sSi[2][1], hj1, sih2);
                    sih3 = fmaf(sSi[3][1], hj1, sih3);
                    sih0 = fmaf(sSi[0][2], hj2, sih0);
                    sih1 = fmaf(sSi[1][2], hj2, sih1);
                    sih2 = fmaf(sSi[2][2], hj2, sih2);
                    sih3 = fmaf(sSi[3][2], hj2, sih3);
                    sih0 = fmaf(sSi[0][3], hj3, sih0);
                    sih1 = fmaf(sSi[1][3], hj3, sih1);
                    sih2 = fmaf(sSi[2][3], hj3, sih2);
                    sih3 = fmaf(sSi[3][3], hj3, sih3);
                }
                float a = sF[i][j];
                a = fmaf(-sFHP[i][0], sih0, a);
                a = fmaf(-sFHP[i][1], sih1, a);
                a = fmaf(-sFHP[i][2], sih2, a);
                a = fmaf(-sFHP[i][3], sih3, a);
                areg = a;
                sA[i][j] = a;
                base[(c4 * 20 + i) * 4 + w] = a;
            }
            if (tid >= 64 && tid < 128) {
                int ii = (tid - 64) >> 2, m = (tid - 64) & 3;
                float acc = 0.f;
#pragma unroll
                for (int n = 0; n < 4; n++) acc = fmaf(sFHP[ii][n], sSi[n][m], acc);
                sL[ii][m] = acc;
                base[(4 * 20 + ii) * 4 + m] = acc;
            } else if (tid >= 128 && tid < 192) {
                int ii = (tid - 128) >> 2, m = (tid - 128) & 3;
                float sir0 = 0.f, sir1 = 0.f, sir2 = 0.f, sir3 = 0.f;
#pragma unroll
                for (int n = 0; n < 4; n++) {
                    float rn = sR[n][m];
                    sir0 = fmaf(sSi[0][n], rn, sir0);
                    sir1 = fmaf(sSi[1][n], rn, sir1);
                    sir2 = fmaf(sSi[2][n], rn, sir2);
                    sir3 = fmaf(sSi[3][n], rn, sir3);
                }
                float acc = sFHP[ii][0] * sir0;
                acc = fmaf(sFHP[ii][1], sir1, acc);
                acc = fmaf(sFHP[ii][2], sir2, acc);
                acc = fmaf(sFHP[ii][3], sir3, acc);
                sLR[ii][m] = acc;
            }
            __syncthreads();   // bar3

            // fused stage4+5 (no intermediate barrier; P double-buffered):
            //   T[i][j] = sum_k A[i][k] P[k][j]   (A row via shfl, T in reg)
            //   HA on warps 6-7, HB on tid 176..191
            //   P'[i][j] = sum_k T[i][k] A[j][k] + sum_m LR[i][m] L[j][m] + Q
            float treg;
            {
                float t0 = 0.f, t1 = 0.f, t2 = 0.f, t3 = 0.f;
#pragma unroll
                for (int k = 0; k < 16; k += 4) {
                    t0 = fmaf(__shfl_sync(0xffffffffu, areg, half | (k + 0)), cur[k + 0][j], t0);
                    t1 = fmaf(__shfl_sync(0xffffffffu, areg, half | (k + 1)), cur[k + 1][j], t1);
                    t2 = fmaf(__shfl_sync(0xffffffffu, areg, half | (k + 2)), cur[k + 2][j], t2);
                    t3 = fmaf(__shfl_sync(0xffffffffu, areg, half | (k + 3)), cur[k + 3][j], t3);
                }
                treg = (t0 + t1) + (t2 + t3);
            }
            if (tid >= 192) {
                int m = (tid - 192) >> 4, jj = tid & 15;
                float acc = 0.f;
#pragma unroll
                for (int k = 0; k < 16; k++) acc = fmaf(sH[m][k], sA[k][jj], acc);
                sHA[m][jj] = acc;
                base[((jj >> 2) * 20 + 16 + m) * 4 + (jj & 3)] = acc;
            } else if (tid >= 176) {
                int m = (tid - 176) >> 2, n = (tid - 176) & 3;
                float acc = 0.f;
#pragma unroll
                for (int k = 0; k < 16; k++) acc = fmaf(sH[m][k], sL[k][n], acc);
                sHB[m][n] = acc;
                base[(4 * 20 + 16 + m) * 4 + n] = acc;
            }
            int flag;
            {
                float a0 = sQ[i][j], a1 = 0.f, a2 = 0.f, a3 = 0.f;
#pragma unroll
                for (int k = 0; k < 16; k += 4) {
                    a0 = fmaf(__shfl_sync(0xffffffffu, treg, half | (k + 0)), sA[j][k + 0], a0);
                    a1 = fmaf(__shfl_sync(0xffffffffu, treg, half | (k + 1)), sA[j][k + 1], a1);
                    a2 = fmaf(__shfl_sync(0xffffffffu, treg, half | (k + 2)), sA[j][k + 2], a2);
                    a3 = fmaf(__shfl_sync(0xffffffffu, treg, half | (k + 3)), sA[j][k + 3], a3);
                }
                float acc = (a0 + a1) + (a2 + a3);
#pragma unroll
                for (int m = 0; m < 4; m++) acc = fmaf(sLR[i][m], sL[j][m], acc);
                float oldp = cur[i][j];
                // NaN-safe (NaN -> flag=1)
                flag = !(fabsf(acc - oldp) <= 2e-3f * fabsf(acc) + 2e-4f);
                nxt[i][j] = acc;
            }
            if (!__syncthreads_or(flag)) {   // bar4 (loop barrier)
                // converged: replicate fixed-point map for remaining steps
                for (int t2 = t + 1; t2 < NSTEP; ++t2) {
                    float* b2 = blob + t2 * 400;
                    b2[(c4 * 20 + i) * 4 + w] = sA[i][j];
                    if (j < 4) b2[(4 * 20 + i) * 4 + j] = sL[i][j];
                    if (i < 4) b2[(c4 * 20 + 16 + i) * 4 + w] = sHA[i][j];
                    if (i < 4 && j < 4) b2[(4 * 20 + 16 + i) * 4 + j] = sHB[i][j];
                }
                __syncthreads();
                if (tid == 0) {
                    __threadfence();
                    *(volatile int*)&g_ready = NCHUNK;
                }
                return;
            }
            if (((t + 1) % CH) == 0) {
                if (tid == 0) {
                    __threadfence();
                    *(volatile int*)&g_ready = (t + 1) / CH;
                }
            }
        }
        return;
    }

    // ==================== CONSUMERS: warp-per-batch scan =====================
    const int lane = tid & 31;
    const int wrp = tid >> 5;
    const int b = ((blockIdx.x - 1) << 3) + wrp;
    const int g = (lane < 20) ? lane : 0;

    // wait for chunk 0 (also guarantees g_s0/g_y0 visible)
    if (tid == 0) {
        while (*(volatile int*)&g_ready < 1) __nanosleep(200);
        __threadfence();
    }
    __syncthreads();

    float x = (lane < 16) ? g_s0[lane] : 0.f;
    float* op = out + b * (NT * NM);
    if (lane >= 16 && lane < 20) op[lane - 16] = g_y0[lane - 16];

    const float4* gb = g_blob;
    const int bb = (blockIdx.x - 1) << 3;

#pragma unroll 1
    for (int c = 0; c < NCHUNK; ++c) {
        if (c > 0) {
            if (tid == 0) {
                while (*(volatile int*)&g_ready < c + 1) __nanosleep(200);
                __threadfence();
            }
            __syncthreads();
        }
        // stage chunk c blob + this block's obs into shared
#pragma unroll
        for (int r = 0; r < 6; r++) {
            int idx = tid + r * 256;
            if (idx < CHF4) sbuf[idx] = gb[c * CHF4 + idx];
        }
        if (tid < 8 * CH) {
            int w2 = tid / CH, s = tid - w2 * CH;
            int tt = c * CH + s;   // <= 254
            sobs[w2][s] = *(const float4*)(inp + ((bb + w2) * NT + tt) * 4);
        }
        __syncthreads();

        const float4* s4 = sbuf;
        int t = c * CH;
#pragma unroll 1
        for (int s = 0; s < CH; ++s, ++t) {
            float4 A[5];
#pragma unroll
            for (int cc = 0; cc < 5; cc++) A[cc] = s4[s * 100 + cc * 20 + g];
            float4 ob = sobs[wrp][s];
            KF_STEP(A, ob, t);
        }
        __syncthreads();  // all readers done before next chunk overwrites
    }
}

extern "C" void kernel_launch(void* const* d_in, const int* in_sizes, int n_in,
                              void* d_out, int out_size) {
    const float* inp = (const float*)d_in[0];
    const float* F   = (const float*)d_in[1];
    const float* H   = (const float*)d_in[2];
    const float* Q   = (const float*)d_in[3];
    const float* R   = (const float*)d_in[4];
    const float* x0  = (const float*)d_in[5];
    const float* sd  = (const float*)d_in[6];
    float* out = (float*)d_out;

    reset_kernel<<<1, 1>>>();
    fused_kernel<<<129, 256>>>(inp, out, F, H, Q, R, x0, sd);
}

// round 13
// speedup vs baseline: 2.0215x; 1.1946x over previous
#include <cuda_runtime.h>

#define NB 1024
#define NT 256
#define NS 16
#define NM 4
#define NSTEP 255
#define ROWF 20
#define CH 15            // chunk: 255 = 17 * 15
#define NCHUNK 17
#define CHF4 (CH * 100)  // float4 per chunk = 1500

// blob[t]: 100 float4 per step, float4-column-major:
//   f4 index (c*20 + row): row<16 state rows, row 16+m measurement rows.
//   Column block c<4 covers matrix cols 4c..4c+3; c==4 covers cols 16..19 (L/HB).
__device__ float4 g_blob[NSTEP * 100];
__device__ float  g_s0[16];
__device__ float  g_y0[4];
__device__ int    g_ready;       // chunks published (monotonic within a launch)
__device__ int    g_conv_chunk;  // first chunk index whose maps are all fixed-point

__global__ void reset_kernel() { g_ready = 0; g_conv_chunk = NCHUNK; }

// ---------------------------------------------------------------------------
// KF consumer step: lanes 0..15 new state, lanes 16..19 write output.
// ---------------------------------------------------------------------------
#define KF_STEP(Ab, ob, tt)                                                    \
    do {                                                                       \
        float acc0, acc1, res;                                                 \
        acc0 = (Ab)[0].x * __shfl_sync(0xffffffffu, x, 0);                     \
        acc1 = (Ab)[0].y * __shfl_sync(0xffffffffu, x, 1);                     \
        acc0 = fmaf((Ab)[0].z, __shfl_sync(0xffffffffu, x, 2), acc0);          \
        acc1 = fmaf((Ab)[0].w, __shfl_sync(0xffffffffu, x, 3), acc1);          \
        acc0 = fmaf((Ab)[1].x, __shfl_sync(0xffffffffu, x, 4), acc0);          \
        acc1 = fmaf((Ab)[1].y, __shfl_sync(0xffffffffu, x, 5), acc1);          \
        acc0 = fmaf((Ab)[1].z, __shfl_sync(0xffffffffu, x, 6), acc0);          \
        acc1 = fmaf((Ab)[1].w, __shfl_sync(0xffffffffu, x, 7), acc1);          \
        acc0 = fmaf((Ab)[2].x, __shfl_sync(0xffffffffu, x, 8), acc0);          \
        acc1 = fmaf((Ab)[2].y, __shfl_sync(0xffffffffu, x, 9), acc1);          \
        acc0 = fmaf((Ab)[2].z, __shfl_sync(0xffffffffu, x, 10), acc0);         \
        acc1 = fmaf((Ab)[2].w, __shfl_sync(0xffffffffu, x, 11), acc1);         \
        acc0 = fmaf((Ab)[3].x, __shfl_sync(0xffffffffu, x, 12), acc0);         \
        acc1 = fmaf((Ab)[3].y, __shfl_sync(0xffffffffu, x, 13), acc1);         \
        acc0 = fmaf((Ab)[3].z, __shfl_sync(0xffffffffu, x, 14), acc0);         \
        acc1 = fmaf((Ab)[3].w, __shfl_sync(0xffffffffu, x, 15), acc1);         \
        acc0 = fmaf((Ab)[4].x, (ob).x, acc0);                                  \
        acc1 = fmaf((Ab)[4].y, (ob).y, acc1);                                  \
        acc0 = fmaf((Ab)[4].z, (ob).z, acc0);                                  \
        acc1 = fmaf((Ab)[4].w, (ob).w, acc1);                                  \
        res = acc0 + acc1;                                                     \
        if (lane < 16) x = res;                                                \
        else if (lane < 20) op[((tt) + 1) * 4 + (lane - 16)] = res;            \
    } while (0)

__global__ __launch_bounds__(256, 1) void fused_kernel(
    const float* __restrict__ inp, float* __restrict__ out,
    const float* __restrict__ F, const float* __restrict__ H,
    const float* __restrict__ Q, const float* __restrict__ R,
    const float* __restrict__ x0, const float* __restrict__ sd)
{
    // producer shared state (P double-buffered)
    __shared__ float sPb[2][16][ROWF];
    __shared__ float sA[16][ROWF];
    __shared__ float sF[16][ROWF];
    __shared__ float sQ[16][ROWF];
    __shared__ float sH[4][ROWF];
    __shared__ float sHP[4][ROWF];
    __shared__ float sHA[4][ROWF];
    __shared__ __align__(16) float sFHP[16][4];
    __shared__ __align__(16) float sL[16][4];
    __shared__ __align__(16) float sLR[16][4];
    __shared__ float sSi[4][4], sR[4][4], sHB[4][4];
    __shared__ float ssd2[16], ss0[16];
    // consumer staging buffers
    __shared__ __align__(16) float4 sbuf[CHF4];   // 24 KB
    __shared__ __align__(16) float4 sobs[8][16];  // 15 used per warp
    __shared__ int sgo;

    const int tid = threadIdx.x;

    if (blockIdx.x == 0) {
        // ============ PRODUCER: Joseph Riccati, 4 barriers/step ============
        const int i = tid >> 4, j = tid & 15;
        const int l = tid & 31;
        const int half = l & 16;   // shfl half-select for row-pair warps

        sF[i][j] = F[i * 16 + j];
        sQ[i][j] = Q[i * 16 + j];
        if (i < 4) sH[i][j] = H[i * 16 + j];
        if (tid < 16) {
            sR[tid >> 2][tid & 3] = R[tid];
            float v = sd[tid];
            ssd2[tid] = v * v;
        }
        __syncthreads();

        // P0 = F diag(sd^2) F^T + Q ; s0 = F x0 ; y0 = H s0
        {
            float a0 = sQ[i][j], a1 = 0.f, a2 = 0.f, a3 = 0.f;
#pragma unroll
            for (int k = 0; k < 16; k += 4) {
                a0 = fmaf(sF[i][k + 0] * ssd2[k + 0], sF[j][k + 0], a0);
                a1 = fmaf(sF[i][k + 1] * ssd2[k + 1], sF[j][k + 1], a1);
                a2 = fmaf(sF[i][k + 2] * ssd2[k + 2], sF[j][k + 2], a2);
                a3 = fmaf(sF[i][k + 3] * ssd2[k + 3], sF[j][k + 3], a3);
            }
            sPb[0][i][j] = (a0 + a1) + (a2 + a3);
        }
        if (tid < 16) {
            float acc = 0.f;
#pragma unroll
            for (int k = 0; k < 16; k++) acc = fmaf(sF[tid][k], x0[k], acc);
            ss0[tid] = acc;
            g_s0[tid] = acc;
        }
        __syncthreads();
        if (tid < 4) {
            float acc = 0.f;
#pragma unroll
            for (int k = 0; k < 16; k++) acc = fmaf(sH[tid][k], ss0[k], acc);
            g_y0[tid] = acc;
        }

        float* blob = (float*)g_blob;
        const int c4 = j >> 2, w = j & 3;

#pragma unroll 1
        for (int t = 0; t < NSTEP; ++t) {
            float* base = blob + t * 400;
            float (*cur)[ROWF] = sPb[t & 1];
            float (*nxt)[ROWF] = sPb[(t + 1) & 1];

            // stage1: HP = H P (64 threads)
            if (tid < 64) {
                int m = tid >> 4, jj = tid & 15;
                float a0 = 0.f, a1 = 0.f, a2 = 0.f, a3 = 0.f;
#pragma unroll
                for (int k = 0; k < 16; k += 4) {
                    a0 = fmaf(sH[m][k + 0], cur[k + 0][jj], a0);
                    a1 = fmaf(sH[m][k + 1], cur[k + 1][jj], a1);
                    a2 = fmaf(sH[m][k + 2], cur[k + 2][jj], a2);
                    a3 = fmaf(sH[m][k + 3], cur[k + 3][jj], a3);
                }
                sHP[m][jj] = (a0 + a1) + (a2 + a3);
            }
            __syncthreads();   // bar1

            // stage2: warp0 (tid<16): S = HP H^T + R and all-shfl 4x4 inverse.
            //         threads 64..127: FHP[i][n] = sum_k F[i][k] * HP[n][k]
            if (tid < 16) {
                int m = tid >> 2, n = tid & 3;
                float s0 = sR[m][n], s1 = 0.f, s2 = 0.f, s3 = 0.f;
#pragma unroll
                for (int k = 0; k < 16; k += 4) {
                    s0 = fmaf(sHP[m][k + 0], sH[n][k + 0], s0);
                    s1 = fmaf(sHP[m][k + 1], sH[n][k + 1], s1);
                    s2 = fmaf(sHP[m][k + 2], sH[n][k + 2], s2);
                    s3 = fmaf(sHP[m][k + 3], sH[n][k + 3], s3);
                }
                float sv = (s0 + s1) + (s2 + s3);   // S[m][n], register only
                // cofactor via 9 shfls (lane r*4+c holds S[r][c])
                int r0 = 0 + (0 >= m), r1 = 1 + (1 >= m), r2 = 2 + (2 >= m);
                int cc0 = 0 + (0 >= n), cc1 = 1 + (1 >= n), cc2 = 2 + (2 >= n);
                float a = __shfl_sync(0xffffu, sv, r0 * 4 + cc0);
                float b = __shfl_sync(0xffffu, sv, r0 * 4 + cc1);
                float c = __shfl_sync(0xffffu, sv, r0 * 4 + cc2);
                float d = __shfl_sync(0xffffu, sv, r1 * 4 + cc0);
                float e = __shfl_sync(0xffffu, sv, r1 * 4 + cc1);
                float f = __shfl_sync(0xffffu, sv, r1 * 4 + cc2);
                float g = __shfl_sync(0xffffu, sv, r2 * 4 + cc0);
                float h = __shfl_sync(0xffffu, sv, r2 * 4 + cc1);
                float i2 = __shfl_sync(0xffffu, sv, r2 * 4 + cc2);
                float minor = a * (e * i2 - f * h) - b * (d * i2 - f * g) + c * (d * h - e * g);
                float cof = ((m + n) & 1) ? -minor : minor;
                // det: butterfly-reduce sv*cof over n (row 0 lanes)
                float dv = sv * cof;
                dv += __shfl_xor_sync(0xffffu, dv, 1);
                dv += __shfl_xor_sync(0xffffu, dv, 2);
                // transpose cofactor (independent of det chain)
                float cofT = __shfl_sync(0xffffu, cof, n * 4 + m);
                float rdet = __fdividef(1.f, dv);
                rdet = __shfl_sync(0xffffu, rdet, 0);
                sSi[m][n] = cofT * rdet;   // Sinv = adj(S)/det
            }
            if (tid >= 64 && tid < 128) {
                int ii = (tid - 64) >> 2, n = (tid - 64) & 3;
                float a0 = 0.f, a1 = 0.f, a2 = 0.f, a3 = 0.f;
#pragma unroll
                for (int k = 0; k < 16; k += 4) {
                    a0 = fmaf(sF[ii][k + 0], sHP[n][k + 0], a0);
                    a1 = fmaf(sF[ii][k + 1], sHP[n][k + 1], a1);
                    a2 = fmaf(sF[ii][k + 2], sHP[n][k + 2], a2);
                    a3 = fmaf(sF[ii][k + 3], sHP[n][k + 3], a3);
                }
                sFHP[ii][n] = (a0 + a1) + (a2 + a3);
            }
            __syncthreads();   // bar2

            // stage3': A = F - FHP*(Si*H) (all, redundant SiH, result kept in reg).
            //          tid 64..127: L = FHP*Si. tid 128..191: LR = FHP*(Si*R).
            float areg;
            {
                float sih0, sih1, sih2, sih3;
                {
                    float hj0 = sH[0][j], hj1 = sH[1][j], hj2 = sH[2][j], hj3 = sH[3][j];
                    sih0 = sSi[0][0] * hj0;
                    sih1 = sSi[1][0] * hj0;
                    sih2 = sSi[2][0] * hj0;
                    sih3 = sSi[3][0] * hj0;
                    sih0 = fmaf(sSi[0][1], hj1, sih0);
                    sih1 = fmaf(sSi[1][1], hj1, sih1);
                    sih2 = fmaf(sSi[2][1], hj1, sih2);
                    sih3 = fmaf(sSi[3][1], hj1, sih3);
                    sih0 = fmaf(sSi[0][2], hj2, sih0);
                    sih1 = fmaf(sSi[1][2], hj2, sih1);
                    sih2 = fmaf(sSi[2][2], hj2, sih2);
                    sih3 = fmaf(sSi[3][2], hj2, sih3);
                    sih0 = fmaf(sSi[0][3], hj3, sih0);
                    sih1 = fmaf(sSi[1][3], hj3, sih1);
                    sih2 = fmaf(sSi[2][3], hj3, sih2);
                    sih3 = fmaf(sSi[3][3], hj3, sih3);
                }
                float a = sF[i][j];
                a = fmaf(-sFHP[i][0], sih0, a);
                a = fmaf(-sFHP[i][1], sih1, a);
                a = fmaf(-sFHP[i][2], sih2, a);
                a = fmaf(-sFHP[i][3], sih3, a);
                areg = a;
                sA[i][j] = a;
                base[(c4 * 20 + i) * 4 + w] = a;
            }
            if (tid >= 64 && tid < 128) {
                int ii = (tid - 64) >> 2, m = (tid - 64) & 3;
                float acc = 0.f;
#pragma unroll
                for (int n = 0; n < 4; n++) acc = fmaf(sFHP[ii][n], sSi[n][m], acc);
                sL[ii][m] = acc;
                base[(4 * 20 + ii) * 4 + m] = acc;
            } else if (tid >= 128 && tid < 192) {
                int ii = (tid - 128) >> 2, m = (tid - 128) & 3;
                float sir0 = 0.f, sir1 = 0.f, sir2 = 0.f, sir3 = 0.f;
#pragma unroll
                for (int n = 0; n < 4; n++) {
                    float rn = sR[n][m];
                    sir0 = fmaf(sSi[0][n], rn, sir0);
                    sir1 = fmaf(sSi[1][n], rn, sir1);
                    sir2 = fmaf(sSi[2][n], rn, sir2);
                    sir3 = fmaf(sSi[3][n], rn, sir3);
                }
                float acc = sFHP[ii][0] * sir0;
                acc = fmaf(sFHP[ii][1], sir1, acc);
                acc = fmaf(sFHP[ii][2], sir2, acc);
                acc = fmaf(sFHP[ii][3], sir3, acc);
                sLR[ii][m] = acc;
            }
            __syncthreads();   // bar3

            // fused stage4+5 (no intermediate barrier; P double-buffered):
            //   T[i][j] = sum_k A[i][k] P[k][j]   (A row via shfl, T in reg)
            //   HA on warps 6-7, HB on tid 176..191
            //   P'[i][j] = sum_k T[i][k] A[j][k] + sum_m LR[i][m] L[j][m] + Q
            float treg;
            {
                float t0 = 0.f, t1 = 0.f, t2 = 0.f, t3 = 0.f;
#pragma unroll
                for (int k = 0; k < 16; k += 4) {
                    t0 = fmaf(__shfl_sync(0xffffffffu, areg, half | (k + 0)), cur[k + 0][j], t0);
                    t1 = fmaf(__shfl_sync(0xffffffffu, areg, half | (k + 1)), cur[k + 1][j], t1);
                    t2 = fmaf(__shfl_sync(0xffffffffu, areg, half | (k + 2)), cur[k + 2][j], t2);
                    t3 = fmaf(__shfl_sync(0xffffffffu, areg, half | (k + 3)), cur[k + 3][j], t3);
                }
                treg = (t0 + t1) + (t2 + t3);
            }
            if (tid >= 192) {
                int m = (tid - 192) >> 4, jj = tid & 15;
                float acc = 0.f;
#pragma unroll
                for (int k = 0; k < 16; k++) acc = fmaf(sH[m][k], sA[k][jj], acc);
                sHA[m][jj] = acc;
                base[((jj >> 2) * 20 + 16 + m) * 4 + (jj & 3)] = acc;
            } else if (tid >= 176) {
                int m = (tid - 176) >> 2, n = (tid - 176) & 3;
                float acc = 0.f;
#pragma unroll
                for (int k = 0; k < 16; k++) acc = fmaf(sH[m][k], sL[k][n], acc);
                sHB[m][n] = acc;
                base[(4 * 20 + 16 + m) * 4 + n] = acc;
            }
            int flag;
            {
                float a0 = sQ[i][j], a1 = 0.f, a2 = 0.f, a3 = 0.f;
#pragma unroll
                for (int k = 0; k < 16; k += 4) {
                    a0 = fmaf(__shfl_sync(0xffffffffu, treg, half | (k + 0)), sA[j][k + 0], a0);
                    a1 = fmaf(__shfl_sync(0xffffffffu, treg, half | (k + 1)), sA[j][k + 1], a1);
                    a2 = fmaf(__shfl_sync(0xffffffffu, treg, half | (k + 2)), sA[j][k + 2], a2);
                    a3 = fmaf(__shfl_sync(0xffffffffu, treg, half | (k + 3)), sA[j][k + 3], a3);
                }
                float acc = (a0 + a1) + (a2 + a3);
#pragma unroll
                for (int m = 0; m < 4; m++) acc = fmaf(sLR[i][m], sL[j][m], acc);
                float oldp = cur[i][j];
                // NaN-safe (NaN -> flag=1)
                flag = !(fabsf(acc - oldp) <= 2e-3f * fabsf(acc) + 2e-4f);
                nxt[i][j] = acc;
            }
            if (!__syncthreads_or(flag)) {   // bar4 (loop barrier)
                // converged: publish constant-tail marker FIRST (fast path
                // never reads the replicated blob), then replicate as the
                // stale-read fallback, then release g_ready.
                if (tid == 0) {
                    __threadfence();
                    *(volatile int*)&g_conv_chunk = (t + CH) / CH;  // ceil((t+1)/CH)
                }
                for (int t2 = t + 1; t2 < NSTEP; ++t2) {
                    float* b2 = blob + t2 * 400;
                    b2[(c4 * 20 + i) * 4 + w] = sA[i][j];
                    if (j < 4) b2[(4 * 20 + i) * 4 + j] = sL[i][j];
                    if (i < 4) b2[(c4 * 20 + 16 + i) * 4 + w] = sHA[i][j];
                    if (i < 4 && j < 4) b2[(4 * 20 + 16 + i) * 4 + j] = sHB[i][j];
                }
                __syncthreads();
                if (tid == 0) {
                    __threadfence();
                    *(volatile int*)&g_ready = NCHUNK;
                }
                return;
            }
            if (((t + 1) % CH) == 0) {
                if (tid == 0) {
                    __threadfence();
                    *(volatile int*)&g_ready = (t + 1) / CH;
                }
            }
        }
        return;
    }

    // ==================== CONSUMERS: warp-per-batch scan =====================
    const int lane = tid & 31;
    const int wrp = tid >> 5;
    const int b = ((blockIdx.x - 1) << 3) + wrp;
    const int g = (lane < 20) ? lane : 0;

    // wait for chunk 0 (also guarantees g_s0/g_y0 visible)
    if (tid == 0) {
        while (*(volatile int*)&g_ready < 1) __nanosleep(100);
        __threadfence();
    }
    __syncthreads();

    float x = (lane < 16) ? g_s0[lane] : 0.f;
    float* op = out + b * (NT * NM);
    const float* ip = inp + b * (NT * NM);
    if (lane >= 16 && lane < 20) op[lane - 16] = g_y0[lane - 16];

    const float4* gb = g_blob;
    const int bb = (blockIdx.x - 1) << 3;

    float4 A[5];     // persists across chunks: holds last step's map
    int t = 0;

#pragma unroll 1
    for (int c = 0; c < NCHUNK; ++c) {
        if (c > 0) {
            // block-uniform decision: stage chunk c, or switch to the
            // constant-map fast path (maps fixed from chunk g_conv_chunk on).
            if (tid == 0) {
                int go = 0;
                for (;;) {
                    if (*(volatile int*)&g_conv_chunk <= c) { go = 1; break; }
                    if (*(volatile int*)&g_ready >= c + 1) break;
                    __nanosleep(100);
                }
                __threadfence();
                sgo = go;
            }
            __syncthreads();
            if (sgo) break;   // uniform exit -> fast path; A = fixed map
        }
        // stage chunk c blob + this block's obs into shared
#pragma unroll
        for (int r = 0; r < 6; r++) {
            int idx = tid + r * 256;
            if (idx < CHF4) sbuf[idx] = gb[c * CHF4 + idx];
        }
        if (tid < 8 * CH) {
            int w2 = tid / CH, s = tid - w2 * CH;
            int tt = c * CH + s;   // <= 254
            sobs[w2][s] = *(const float4*)(inp + ((bb + w2) * NT + tt) * 4);
        }
        __syncthreads();

        const float4* s4 = sbuf;
#pragma unroll 1
        for (int s = 0; s < CH; ++s, ++t) {
#pragma unroll
            for (int cc = 0; cc < 5; cc++) A[cc] = s4[s * 100 + cc * 20 + g];
            float4 ob = sobs[wrp][s];
            KF_STEP(A, ob, t);
        }
        __syncthreads();  // all readers done before next chunk overwrites
    }

    // ---- constant-map fast path: barrier-free, obs prefetched 3 deep ----
    if (t < NSTEP) {
        float4 o0 = *(const float4*)(ip + t * 4);
        float4 o1 = (t + 1 < NSTEP) ? *(const float4*)(ip + (t + 1) * 4) : o0;
        float4 o2 = (t + 2 < NSTEP) ? *(const float4*)(ip + (t + 2) * 4) : o0;
#pragma unroll 3
        for (; t < NSTEP; ++t) {
            int tn = (t + 3 < NSTEP) ? t + 3 : t;
            float4 on = *(const float4*)(ip + tn * 4);
            KF_STEP(A, o0, t);
            o0 = o1; o1 = o2; o2 = on;
        }
    }
}

extern "C" void kernel_launch(void* const* d_in, const int* in_sizes, int n_in,
                              void* d_out, int out_size) {
    const float* inp = (const float*)d_in[0];
    const float* F   = (const float*)d_in[1];
    const float* H   = (const float*)d_in[2];
    const float* Q   = (const float*)d_in[3];
    const float* R   = (const float*)d_in[4];
    const float* x0  = (const float*)d_in[5];
    const float* sd  = (const float*)d_in[6];
    float* out = (float*)d_out;

    reset_kernel<<<1, 1>>>();
    fused_kernel<<<129, 256>>>(inp, out, F, H, Q, R, x0, sd);
}

// round 14
// speedup vs baseline: 2.0710x; 1.0245x over previous
#include <cuda_runtime.h>

#define NB 1024
#define NT 256
#define NS 16
#define NM 4
#define NSTEP 255
#define ROWF 20
#define CH 15            // chunk: 255 = 17 * 15
#define NCHUNK 17
#define CHF4 (CH * 100)  // float4 per chunk = 1500

// blob[t]: 100 float4 per step, float4-column-major:
//   f4 index (c*20 + row): row<16 state rows, row 16+m measurement rows.
//   Column block c<4 covers matrix cols 4c..4c+3; c==4 covers cols 16..19 (L/HB).
__device__ float4 g_blob[NSTEP * 100];
__device__ float  g_s0[16];
__device__ float  g_y0[4];
__device__ int    g_ready;       // chunks published (monotonic within a launch)
__device__ int    g_conv_chunk;  // first chunk index whose maps are all fixed-point

__global__ void reset_kernel() { g_ready = 0; g_conv_chunk = NCHUNK; }

// ---------------------------------------------------------------------------
// KF consumer step: lanes 0..15 new state, lanes 16..19 write output.
// ---------------------------------------------------------------------------
#define KF_STEP(Ab, ob, tt)                                                    \
    do {                                                                       \
        float acc0, acc1, res;                                                 \
        acc0 = (Ab)[0].x * __shfl_sync(0xffffffffu, x, 0);                     \
        acc1 = (Ab)[0].y * __shfl_sync(0xffffffffu, x, 1);                     \
        acc0 = fmaf((Ab)[0].z, __shfl_sync(0xffffffffu, x, 2), acc0);          \
        acc1 = fmaf((Ab)[0].w, __shfl_sync(0xffffffffu, x, 3), acc1);          \
        acc0 = fmaf((Ab)[1].x, __shfl_sync(0xffffffffu, x, 4), acc0);          \
        acc1 = fmaf((Ab)[1].y, __shfl_sync(0xffffffffu, x, 5), acc1);          \
        acc0 = fmaf((Ab)[1].z, __shfl_sync(0xffffffffu, x, 6), acc0);          \
        acc1 = fmaf((Ab)[1].w, __shfl_sync(0xffffffffu, x, 7), acc1);          \
        acc0 = fmaf((Ab)[2].x, __shfl_sync(0xffffffffu, x, 8), acc0);          \
        acc1 = fmaf((Ab)[2].y, __shfl_sync(0xffffffffu, x, 9), acc1);          \
        acc0 = fmaf((Ab)[2].z, __shfl_sync(0xffffffffu, x, 10), acc0);         \
        acc1 = fmaf((Ab)[2].w, __shfl_sync(0xffffffffu, x, 11), acc1);         \
        acc0 = fmaf((Ab)[3].x, __shfl_sync(0xffffffffu, x, 12), acc0);         \
        acc1 = fmaf((Ab)[3].y, __shfl_sync(0xffffffffu, x, 13), acc1);         \
        acc0 = fmaf((Ab)[3].z, __shfl_sync(0xffffffffu, x, 14), acc0);         \
        acc1 = fmaf((Ab)[3].w, __shfl_sync(0xffffffffu, x, 15), acc1);         \
        acc0 = fmaf((Ab)[4].x, (ob).x, acc0);                                  \
        acc1 = fmaf((Ab)[4].y, (ob).y, acc1);                                  \
        acc0 = fmaf((Ab)[4].z, (ob).z, acc0);                                  \
        acc1 = fmaf((Ab)[4].w, (ob).w, acc1);                                  \
        res = acc0 + acc1;                                                     \
        if (lane < 16) x = res;                                                \
        else if (lane < 20) op[((tt) + 1) * 4 + (lane - 16)] = res;            \
    } while (0)

__global__ __launch_bounds__(256, 1) void fused_kernel(
    const float* __restrict__ inp, float* __restrict__ out,
    const float* __restrict__ F, const float* __restrict__ H,
    const float* __restrict__ Q, const float* __restrict__ R,
    const float* __restrict__ x0, const float* __restrict__ sd)
{
    // producer shared state (P double-buffered)
    __shared__ float sPb[2][16][ROWF];
    __shared__ float sA[16][ROWF];
    __shared__ float sF[16][ROWF];
    __shared__ float sQ[16][ROWF];
    __shared__ float sH[4][ROWF];
    __shared__ float sHP[4][ROWF];
    __shared__ float sHA[4][ROWF];
    __shared__ __align__(16) float sFHP[16][4];
    __shared__ __align__(16) float sL[16][4];
    __shared__ __align__(16) float sLR[16][4];
    __shared__ float sSi[4][4], sR[4][4], sHB[4][4];
    __shared__ float ssd2[16], ss0[16];
    // consumer staging buffers
    __shared__ __align__(16) float4 sbuf[CHF4];   // 24 KB
    __shared__ __align__(16) float4 sobs[8][16];  // 15 used per warp
    __shared__ int sgo;

    const int tid = threadIdx.x;

    if (blockIdx.x == 0) {
        // ============ PRODUCER: Joseph Riccati, 4 barriers/step ============
        // T = A*P computed distributively: T = F*P - L*(H*P), with F*P kept
        // register-resident per thread and L-row recomputed redundantly.
        const int i = tid >> 4, j = tid & 15;
        const int l = tid & 31;
        const int half = l & 16;   // shfl half-select for row-pair warps

        sF[i][j] = F[i * 16 + j];
        sQ[i][j] = Q[i * 16 + j];
        if (i < 4) sH[i][j] = H[i * 16 + j];
        if (tid < 16) {
            sR[tid >> 2][tid & 3] = R[tid];
            float v = sd[tid];
            ssd2[tid] = v * v;
        }
        __syncthreads();

        // P0 = F diag(sd^2) F^T + Q ; s0 = F x0 ; y0 = H s0
        {
            float a0 = sQ[i][j], a1 = 0.f, a2 = 0.f, a3 = 0.f;
#pragma unroll
            for (int k = 0; k < 16; k += 4) {
                a0 = fmaf(sF[i][k + 0] * ssd2[k + 0], sF[j][k + 0], a0);
                a1 = fmaf(sF[i][k + 1] * ssd2[k + 1], sF[j][k + 1], a1);
                a2 = fmaf(sF[i][k + 2] * ssd2[k + 2], sF[j][k + 2], a2);
                a3 = fmaf(sF[i][k + 3] * ssd2[k + 3], sF[j][k + 3], a3);
            }
            sPb[0][i][j] = (a0 + a1) + (a2 + a3);
        }
        if (tid < 16) {
            float acc = 0.f;
#pragma unroll
            for (int k = 0; k < 16; k++) acc = fmaf(sF[tid][k], x0[k], acc);
            ss0[tid] = acc;
            g_s0[tid] = acc;
        }
        __syncthreads();
        if (tid < 4) {
            float acc = 0.f;
#pragma unroll
            for (int k = 0; k < 16; k++) acc = fmaf(sH[tid][k], ss0[k], acc);
            g_y0[tid] = acc;
        }

        float* blob = (float*)g_blob;
        const int c4 = j >> 2, w = j & 3;

#pragma unroll 1
        for (int t = 0; t < NSTEP; ++t) {
            float* base = blob + t * 400;
            float (*cur)[ROWF] = sPb[t & 1];
            float (*nxt)[ROWF] = sPb[(t + 1) & 1];

            // stage1: FP[i][j] = sum_k F[i][k] P[k][j] (ALL threads, reg).
            //         HP = H P on warps 6-7 (tid 192..255).
            float fpreg;
            {
                float a0 = 0.f, a1 = 0.f, a2 = 0.f, a3 = 0.f;
#pragma unroll
                for (int k = 0; k < 16; k += 4) {
                    a0 = fmaf(sF[i][k + 0], cur[k + 0][j], a0);
                    a1 = fmaf(sF[i][k + 1], cur[k + 1][j], a1);
                    a2 = fmaf(sF[i][k + 2], cur[k + 2][j], a2);
                    a3 = fmaf(sF[i][k + 3], cur[k + 3][j], a3);
                }
                fpreg = (a0 + a1) + (a2 + a3);
            }
            if (tid >= 192) {
                int m = (tid - 192) >> 4, jj = tid & 15;
                float a0 = 0.f, a1 = 0.f, a2 = 0.f, a3 = 0.f;
#pragma unroll
                for (int k = 0; k < 16; k += 4) {
                    a0 = fmaf(sH[m][k + 0], cur[k + 0][jj], a0);
                    a1 = fmaf(sH[m][k + 1], cur[k + 1][jj], a1);
                    a2 = fmaf(sH[m][k + 2], cur[k + 2][jj], a2);
                    a3 = fmaf(sH[m][k + 3], cur[k + 3][jj], a3);
                }
                sHP[m][jj] = (a0 + a1) + (a2 + a3);
            }
            __syncthreads();   // bar1

            // stage2: warp0 (tid<16): S = HP H^T + R and all-shfl 4x4 inverse.
            //         threads 64..127: FHP[i][n] = sum_k F[i][k] * HP[n][k]
            if (tid < 16) {
                int m = tid >> 2, n = tid & 3;
                float s0 = sR[m][n], s1 = 0.f, s2 = 0.f, s3 = 0.f;
#pragma unroll
                for (int k = 0; k < 16; k += 4) {
                    s0 = fmaf(sHP[m][k + 0], sH[n][k + 0], s0);
                    s1 = fmaf(sHP[m][k + 1], sH[n][k + 1], s1);
                    s2 = fmaf(sHP[m][k + 2], sH[n][k + 2], s2);
                    s3 = fmaf(sHP[m][k + 3], sH[n][k + 3], s3);
                }
                float sv = (s0 + s1) + (s2 + s3);   // S[m][n], register only
                // cofactor via 9 shfls (lane r*4+c holds S[r][c])
                int r0 = 0 + (0 >= m), r1 = 1 + (1 >= m), r2 = 2 + (2 >= m);
                int cc0 = 0 + (0 >= n), cc1 = 1 + (1 >= n), cc2 = 2 + (2 >= n);
                float a = __shfl_sync(0xffffu, sv, r0 * 4 + cc0);
                float b = __shfl_sync(0xffffu, sv, r0 * 4 + cc1);
                float c = __shfl_sync(0xffffu, sv, r0 * 4 + cc2);
                float d = __shfl_sync(0xffffu, sv, r1 * 4 + cc0);
                float e = __shfl_sync(0xffffu, sv, r1 * 4 + cc1);
                float f = __shfl_sync(0xffffu, sv, r1 * 4 + cc2);
                float g = __shfl_sync(0xffffu, sv, r2 * 4 + cc0);
                float h = __shfl_sync(0xffffu, sv, r2 * 4 + cc1);
                float i2 = __shfl_sync(0xffffu, sv, r2 * 4 + cc2);
                float minor = a * (e * i2 - f * h) - b * (d * i2 - f * g) + c * (d * h - e * g);
                float cof = ((m + n) & 1) ? -minor : minor;
                // det: butterfly-reduce sv*cof over n (row 0 lanes)
                float dv = sv * cof;
                dv += __shfl_xor_sync(0xffffu, dv, 1);
                dv += __shfl_xor_sync(0xffffu, dv, 2);
                // transpose cofactor (independent of det chain)
                float cofT = __shfl_sync(0xffffu, cof, n * 4 + m);
                float rdet = __fdividef(1.f, dv);
                rdet = __shfl_sync(0xffffu, rdet, 0);
                sSi[m][n] = cofT * rdet;   // Sinv = adj(S)/det
            }
            if (tid >= 64 && tid < 128) {
                int ii = (tid - 64) >> 2, n = (tid - 64) & 3;
                float a0 = 0.f, a1 = 0.f, a2 = 0.f, a3 = 0.f;
#pragma unroll
                for (int k = 0; k < 16; k += 4) {
                    a0 = fmaf(sF[ii][k + 0], sHP[n][k + 0], a0);
                    a1 = fmaf(sF[ii][k + 1], sHP[n][k + 1], a1);
                    a2 = fmaf(sF[ii][k + 2], sHP[n][k + 2], a2);
                    a3 = fmaf(sF[ii][k + 3], sHP[n][k + 3], a3);
                }
                sFHP[ii][n] = (a0 + a1) + (a2 + a3);
            }
            __syncthreads();   // bar2

            // stage3': ALL threads redundantly compute L-row i, then
            //   A[i][j] = F - Lrow.Hcol_j ; treg = FP - Lrow.HPcol_j.
            //   tid 64..127: L -> smem/blob. tid 128..191: LR = FHP*(Si*R).
            float areg, treg;
            {
                float L0, L1, L2, L3;
                {
                    float f0 = sFHP[i][0], f1 = sFHP[i][1], f2 = sFHP[i][2], f3 = sFHP[i][3];
                    L0 = f0 * sSi[0][0];
                    L1 = f0 * sSi[0][1];
                    L2 = f0 * sSi[0][2];
                    L3 = f0 * sSi[0][3];
                    L0 = fmaf(f1, sSi[1][0], L0);
                    L1 = fmaf(f1, sSi[1][1], L1);
                    L2 = fmaf(f1, sSi[1][2], L2);
                    L3 = fmaf(f1, sSi[1][3], L3);
                    L0 = fmaf(f2, sSi[2][0], L0);
                    L1 = fmaf(f2, sSi[2][1], L1);
                    L2 = fmaf(f2, sSi[2][2], L2);
                    L3 = fmaf(f2, sSi[2][3], L3);
                    L0 = fmaf(f3, sSi[3][0], L0);
                    L1 = fmaf(f3, sSi[3][1], L1);
                    L2 = fmaf(f3, sSi[3][2], L2);
                    L3 = fmaf(f3, sSi[3][3], L3);
                }
                float a = sF[i][j];
                a = fmaf(-L0, sH[0][j], a);
                a = fmaf(-L1, sH[1][j], a);
                a = fmaf(-L2, sH[2][j], a);
                a = fmaf(-L3, sH[3][j], a);
                areg = a;
                sA[i][j] = a;
                base[(c4 * 20 + i) * 4 + w] = a;
                float tt = fpreg;
                tt = fmaf(-L0, sHP[0][j], tt);
                tt = fmaf(-L1, sHP[1][j], tt);
                tt = fmaf(-L2, sHP[2][j], tt);
                tt = fmaf(-L3, sHP[3][j], tt);
                treg = tt;
                if (tid >= 64 && tid < 128) {
                    // this thread's (i = 4..7) Lrow lanes m = j&3? No —
                    // dedicated write below uses the classic mapping.
                }
            }
            if (tid >= 64 && tid < 128) {
                int ii = (tid - 64) >> 2, m = (tid - 64) & 3;
                float acc = 0.f;
#pragma unroll
                for (int n = 0; n < 4; n++) acc = fmaf(sFHP[ii][n], sSi[n][m], acc);
                sL[ii][m] = acc;
                base[(4 * 20 + ii) * 4 + m] = acc;
            } else if (tid >= 128 && tid < 192) {
                int ii = (tid - 128) >> 2, m = (tid - 128) & 3;
                float sir0 = 0.f, sir1 = 0.f, sir2 = 0.f, sir3 = 0.f;
#pragma unroll
                for (int n = 0; n < 4; n++) {
                    float rn = sR[n][m];
                    sir0 = fmaf(sSi[0][n], rn, sir0);
                    sir1 = fmaf(sSi[1][n], rn, sir1);
                    sir2 = fmaf(sSi[2][n], rn, sir2);
                    sir3 = fmaf(sSi[3][n], rn, sir3);
                }
                float acc = sFHP[ii][0] * sir0;
                acc = fmaf(sFHP[ii][1], sir1, acc);
                acc = fmaf(sFHP[ii][2], sir2, acc);
                acc = fmaf(sFHP[ii][3], sir3, acc);
                sLR[ii][m] = acc;
            }
            __syncthreads();   // bar3

            // stage4': P' = T A^T + LR L^T + Q (T row via shfl of treg);
            //          HA on warps 6-7, HB on tid 176..191.
            if (tid >= 192) {
                int m = (tid - 192) >> 4, jj = tid & 15;
                float acc = 0.f;
#pragma unroll
                for (int k = 0; k < 16; k++) acc = fmaf(sH[m][k], sA[k][jj], acc);
                sHA[m][jj] = acc;
                base[((jj >> 2) * 20 + 16 + m) * 4 + (jj & 3)] = acc;
            } else if (tid >= 176) {
                int m = (tid - 176) >> 2, n = (tid - 176) & 3;
                float acc = 0.f;
#pragma unroll
                for (int k = 0; k < 16; k++) acc = fmaf(sH[m][k], sL[k][n], acc);
                sHB[m][n] = acc;
                base[(4 * 20 + 16 + m) * 4 + n] = acc;
            }
            int flag;
            {
                float a0 = sQ[i][j], a1 = 0.f, a2 = 0.f, a3 = 0.f;
#pragma unroll
                for (int k = 0; k < 16; k += 4) {
                    a0 = fmaf(__shfl_sync(0xffffffffu, treg, half | (k + 0)), sA[j][k + 0], a0);
                    a1 = fmaf(__shfl_sync(0xffffffffu, treg, half | (k + 1)), sA[j][k + 1], a1);
                    a2 = fmaf(__shfl_sync(0xffffffffu, treg, half | (k + 2)), sA[j][k + 2], a2);
                    a3 = fmaf(__shfl_sync(0xffffffffu, treg, half | (k + 3)), sA[j][k + 3], a3);
                }
                float acc = (a0 + a1) + (a2 + a3);
#pragma unroll
                for (int m = 0; m < 4; m++) acc = fmaf(sLR[i][m], sL[j][m], acc);
                float oldp = cur[i][j];
                // NaN-safe (NaN -> flag=1)
                flag = !(fabsf(acc - oldp) <= 2e-3f * fabsf(acc) + 2e-4f);
                nxt[i][j] = acc;
            }
            if (!__syncthreads_or(flag)) {   // bar4 (loop barrier)
                // converged: publish constant-tail marker FIRST (fast path
                // never reads the replicated blob), then replicate as the
                // stale-read fallback, then release g_ready.
                if (tid == 0) {
                    __threadfence();
                    *(volatile int*)&g_conv_chunk = (t + CH) / CH;  // ceil((t+1)/CH)
                }
                for (int t2 = t + 1; t2 < NSTEP; ++t2) {
                    float* b2 = blob + t2 * 400;
                    b2[(c4 * 20 + i) * 4 + w] = sA[i][j];
                    if (j < 4) b2[(4 * 20 + i) * 4 + j] = sL[i][j];
                    if (i < 4) b2[(c4 * 20 + 16 + i) * 4 + w] = sHA[i][j];
                    if (i < 4 && j < 4) b2[(4 * 20 + 16 + i) * 4 + j] = sHB[i][j];
                }
                __syncthreads();
                if (tid == 0) {
                    __threadfence();
                    *(volatile int*)&g_ready = NCHUNK;
                }
                return;
            }
            if (((t + 1) % CH) == 0) {
                if (tid == 0) {
                    __threadfence();
                    *(volatile int*)&g_ready = (t + 1) / CH;
                }
            }
        }
        return;
    }

    // ==================== CONSUMERS: warp-per-batch scan =====================
    const int lane = tid & 31;
    const int wrp = tid >> 5;
    const int b = ((blockIdx.x - 1) << 3) + wrp;
    const int g = (lane < 20) ? lane : 0;

    // wait for chunk 0 (also guarantees g_s0/g_y0 visible)
    if (tid == 0) {
        while (*(volatile int*)&g_ready < 1) __nanosleep(100);
        __threadfence();
    }
    __syncthreads();

    float x = (lane < 16) ? g_s0[lane] : 0.f;
    float* op = out + b * (NT * NM);
    const float* ip = inp + b * (NT * NM);
    if (lane >= 16 && lane < 20) op[lane - 16] = g_y0[lane - 16];

    const float4* gb = g_blob;
    const int bb = (blockIdx.x - 1) << 3;

    float4 A[5];     // persists across chunks: holds last step's map
    int t = 0;

#pragma unroll 1
    for (int c = 0; c < NCHUNK; ++c) {
        if (c > 0) {
            // block-uniform decision: stage chunk c, or switch to the
            // constant-map fast path (maps fixed from chunk g_conv_chunk on).
            if (tid == 0) {
                int go = 0;
                for (;;) {
                    if (*(volatile int*)&g_conv_chunk <= c) { go = 1; break; }
                    if (*(volatile int*)&g_ready >= c + 1) break;
                    __nanosleep(100);
                }
                __threadfence();
                sgo = go;
            }
            __syncthreads();
            if (sgo) break;   // uniform exit -> fast path; A = fixed map
        }
        // stage chunk c blob + this block's obs into shared
#pragma unroll
        for (int r = 0; r < 6; r++) {
            int idx = tid + r * 256;
            if (idx < CHF4) sbuf[idx] = gb[c * CHF4 + idx];
        }
        if (tid < 8 * CH) {
            int w2 = tid / CH, s = tid - w2 * CH;
            int tt = c * CH + s;   // <= 254
            sobs[w2][s] = *(const float4*)(inp + ((bb + w2) * NT + tt) * 4);
        }
        __syncthreads();

        const float4* s4 = sbuf;
#pragma unroll 1
        for (int s = 0; s < CH; ++s, ++t) {
#pragma unroll
            for (int cc = 0; cc < 5; cc++) A[cc] = s4[s * 100 + cc * 20 + g];
            float4 ob = sobs[wrp][s];
            KF_STEP(A, ob, t);
        }
        __syncthreads();  // all readers done before next chunk overwrites
    }

    // ---- constant-map fast path: barrier-free, obs prefetched 3 deep ----
    if (t < NSTEP) {
        float4 o0 = *(const float4*)(ip + t * 4);
        float4 o1 = (t + 1 < NSTEP) ? *(const float4*)(ip + (t + 1) * 4) : o0;
        float4 o2 = (t + 2 < NSTEP) ? *(const float4*)(ip + (t + 2) * 4) : o0;
#pragma unroll 3
        for (; t < NSTEP; ++t) {
            int tn = (t + 3 < NSTEP) ? t + 3 : t;
            float4 on = *(const float4*)(ip + tn * 4);
            KF_STEP(A, o0, t);
            o0 = o1; o1 = o2; o2 = on;
        }
    }
}

extern "C" void kernel_launch(void* const* d_in, const int* in_sizes, int n_in,
                              void* d_out, int out_size) {
    const float* inp = (const float*)d_in[0];
    const float* F   = (const float*)d_in[1];
    const float* H   = (const float*)d_in[2];
    const float* Q   = (const float*)d_in[3];
    const float* R   = (const float*)d_in[4];
    const float* x0  = (const float*)d_in[5];
    const float* sd  = (const float*)d_in[6];
    float* out = (float*)d_out;

    reset_kernel<<<1, 1>>>();
    fused_kernel<<<129, 256>>>(inp, out, F, H, Q, R, x0, sd);
}

// round 15
// speedup vs baseline: 2.0733x; 1.0011x over previous
#include <cuda_runtime.h>

#define NB 1024
#define NT 256
#define NS 16
#define NM 4
#define NSTEP 255
#define ROWF 20
#define CH 15            // chunk: 255 = 17 * 15
#define NCHUNK 17
#define CHF4 (CH * 100)  // float4 per chunk = 1500

// blob[t]: 100 float4 per step, float4-column-major:
//   f4 index (c*20 + row): row<16 state rows, row 16+m measurement rows.
//   Column block c<4 covers matrix cols 4c..4c+3; c==4 covers cols 16..19 (L/HB).
__device__ float4 g_blob[NSTEP * 100];
__device__ float  g_s0[16];
__device__ float  g_y0[4];
__device__ int    g_ready;       // chunks published (monotonic within a launch)
__device__ int    g_conv_chunk;  // first chunk index whose maps are all fixed-point

__global__ void reset_kernel() { g_ready = 0; g_conv_chunk = NCHUNK; }

// ---------------------------------------------------------------------------
// KF consumer step: lanes 0..15 new state, lanes 16..19 write output.
// ---------------------------------------------------------------------------
#define KF_STEP(Ab, ob, tt)                                                    \
    do {                                                                       \
        float acc0, acc1, res;                                                 \
        acc0 = (Ab)[0].x * __shfl_sync(0xffffffffu, x, 0);                     \
        acc1 = (Ab)[0].y * __shfl_sync(0xffffffffu, x, 1);                     \
        acc0 = fmaf((Ab)[0].z, __shfl_sync(0xffffffffu, x, 2), acc0);          \
        acc1 = fmaf((Ab)[0].w, __shfl_sync(0xffffffffu, x, 3), acc1);          \
        acc0 = fmaf((Ab)[1].x, __shfl_sync(0xffffffffu, x, 4), acc0);          \
        acc1 = fmaf((Ab)[1].y, __shfl_sync(0xffffffffu, x, 5), acc1);          \
        acc0 = fmaf((Ab)[1].z, __shfl_sync(0xffffffffu, x, 6), acc0);          \
        acc1 = fmaf((Ab)[1].w, __shfl_sync(0xffffffffu, x, 7), acc1);          \
        acc0 = fmaf((Ab)[2].x, __shfl_sync(0xffffffffu, x, 8), acc0);          \
        acc1 = fmaf((Ab)[2].y, __shfl_sync(0xffffffffu, x, 9), acc1);          \
        acc0 = fmaf((Ab)[2].z, __shfl_sync(0xffffffffu, x, 10), acc0);         \
        acc1 = fmaf((Ab)[2].w, __shfl_sync(0xffffffffu, x, 11), acc1);         \
        acc0 = fmaf((Ab)[3].x, __shfl_sync(0xffffffffu, x, 12), acc0);         \
        acc1 = fmaf((Ab)[3].y, __shfl_sync(0xffffffffu, x, 13), acc1);         \
        acc0 = fmaf((Ab)[3].z, __shfl_sync(0xffffffffu, x, 14), acc0);         \
        acc1 = fmaf((Ab)[3].w, __shfl_sync(0xffffffffu, x, 15), acc1);         \
        acc0 = fmaf((Ab)[4].x, (ob).x, acc0);                                  \
        acc1 = fmaf((Ab)[4].y, (ob).y, acc1);                                  \
        acc0 = fmaf((Ab)[4].z, (ob).z, acc0);                                  \
        acc1 = fmaf((Ab)[4].w, (ob).w, acc1);                                  \
        res = acc0 + acc1;                                                     \
        if (lane < 16) x = res;                                                \
        else if (lane < 20) op[((tt) + 1) * 4 + (lane - 16)] = res;            \
    } while (0)

__global__ __launch_bounds__(256, 1) void fused_kernel(
    const float* __restrict__ inp, float* __restrict__ out,
    const float* __restrict__ F, const float* __restrict__ H,
    const float* __restrict__ Q, const float* __restrict__ R,
    const float* __restrict__ x0, const float* __restrict__ sd)
{
    // producer shared state (P double-buffered)
    __shared__ float sPb[2][16][ROWF];
    __shared__ float sA[16][ROWF];
    __shared__ float sF[16][ROWF];
    __shared__ float sQ[16][ROWF];
    __shared__ float sH[4][ROWF];
    __shared__ float sHP[4][ROWF];
    __shared__ float sHA[4][ROWF];
    __shared__ float sFP01[2][ROWF];
    __shared__ __align__(16) float sFHP[16][4];
    __shared__ __align__(16) float sL[16][4];
    __shared__ __align__(16) float sLR[16][4];
    __shared__ float sSi[4][4], sR[4][4], sHB[4][4];
    __shared__ float ssd2[16], ss0[16];
    // consumer staging buffers
    __shared__ __align__(16) float4 sbuf[CHF4];   // 24 KB
    __shared__ __align__(16) float4 sobs[8][16];  // 15 used per warp
    __shared__ int sgo;

    const int tid = threadIdx.x;

    if (blockIdx.x == 0) {
        // ============ PRODUCER: Joseph Riccati, 3 full barriers/step =======
        // bar1 replaced by a named producer-consumer barrier: warp0 computes
        // HP itself, bar.arrive's, and runs the S+inverse chain immediately;
        // warps 1-7 compute FP (warps 6-7 also FP rows 0,1 for warp0) and
        // bar.sync before FHP.
        const int i = tid >> 4, j = tid & 15;
        const int l = tid & 31;
        const int wp = tid >> 5;
        const int half = l & 16;   // shfl half-select for row-pair warps

        sF[i][j] = F[i * 16 + j];
        sQ[i][j] = Q[i * 16 + j];
        if (i < 4) sH[i][j] = H[i * 16 + j];
        if (tid < 16) {
            sR[tid >> 2][tid & 3] = R[tid];
            float v = sd[tid];
            ssd2[tid] = v * v;
        }
        __syncthreads();

        // warp0 register preload: H rows (l>>4) and (l>>4)+2 for its HP dots
        float hA0[16], hA2[16];
        if (wp == 0) {
#pragma unroll
            for (int k = 0; k < 16; k++) {
                hA0[k] = sH[l >> 4][k];
                hA2[k] = sH[(l >> 4) + 2][k];
            }
        }

        // P0 = F diag(sd^2) F^T + Q ; s0 = F x0 ; y0 = H s0
        {
            float a0 = sQ[i][j], a1 = 0.f, a2 = 0.f, a3 = 0.f;
#pragma unroll
            for (int k = 0; k < 16; k += 4) {
                a0 = fmaf(sF[i][k + 0] * ssd2[k + 0], sF[j][k + 0], a0);
                a1 = fmaf(sF[i][k + 1] * ssd2[k + 1], sF[j][k + 1], a1);
                a2 = fmaf(sF[i][k + 2] * ssd2[k + 2], sF[j][k + 2], a2);
                a3 = fmaf(sF[i][k + 3] * ssd2[k + 3], sF[j][k + 3], a3);
            }
            sPb[0][i][j] = (a0 + a1) + (a2 + a3);
        }
        if (tid < 16) {
            float acc = 0.f;
#pragma unroll
            for (int k = 0; k < 16; k++) acc = fmaf(sF[tid][k], x0[k], acc);
            ss0[tid] = acc;
            g_s0[tid] = acc;
        }
        __syncthreads();
        if (tid < 4) {
            float acc = 0.f;
#pragma unroll
            for (int k = 0; k < 16; k++) acc = fmaf(sH[tid][k], ss0[k], acc);
            g_y0[tid] = acc;
        }

        float* blob = (float*)g_blob;
        const int c4 = j >> 2, w = j & 3;

#pragma unroll 1
        for (int t = 0; t < NSTEP; ++t) {
            float* base = blob + t * 400;
            float (*cur)[ROWF] = sPb[t & 1];
            float (*nxt)[ROWF] = sPb[(t + 1) & 1];

            float fpreg = 0.f;
            if (wp == 0) {
                // --- warp0: HP rows (l>>4), (l>>4)+2 at column jj=l&15 ---
                const int jj = l & 15;
                const int m0 = l >> 4;
                {
                    float a0 = 0.f, a1 = 0.f, a2 = 0.f, a3 = 0.f;
#pragma unroll
                    for (int k = 0; k < 16; k += 2) {
                        float p0 = cur[k][jj], p1 = cur[k + 1][jj];
                        a0 = fmaf(hA0[k], p0, a0);
                        a1 = fmaf(hA0[k + 1], p1, a1);
                        a2 = fmaf(hA2[k], p0, a2);
                        a3 = fmaf(hA2[k + 1], p1, a3);
                    }
                    sHP[m0][jj] = a0 + a1;
                    sHP[m0 + 2][jj] = a2 + a3;
                }
                asm volatile("bar.arrive 1, 256;" ::: "memory");
                __syncwarp();
                // --- S = HP H^T + R and all-shfl 4x4 inverse (lanes 0-15) ---
                if (l < 16) {
                    int m = l >> 2, n = l & 3;
                    float s0 = sR[m][n], s1 = 0.f, s2 = 0.f, s3 = 0.f;
#pragma unroll
                    for (int k = 0; k < 16; k += 4) {
                        s0 = fmaf(sHP[m][k + 0], sH[n][k + 0], s0);
                        s1 = fmaf(sHP[m][k + 1], sH[n][k + 1], s1);
                        s2 = fmaf(sHP[m][k + 2], sH[n][k + 2], s2);
                        s3 = fmaf(sHP[m][k + 3], sH[n][k + 3], s3);
                    }
                    float sv = (s0 + s1) + (s2 + s3);   // S[m][n], register only
                    int r0 = 0 + (0 >= m), r1 = 1 + (1 >= m), r2 = 2 + (2 >= m);
                    int cc0 = 0 + (0 >= n), cc1 = 1 + (1 >= n), cc2 = 2 + (2 >= n);
                    float a = __shfl_sync(0xffffu, sv, r0 * 4 + cc0);
                    float b = __shfl_sync(0xffffu, sv, r0 * 4 + cc1);
                    float c = __shfl_sync(0xffffu, sv, r0 * 4 + cc2);
                    float d = __shfl_sync(0xffffu, sv, r1 * 4 + cc0);
                    float e = __shfl_sync(0xffffu, sv, r1 * 4 + cc1);
                    float f = __shfl_sync(0xffffu, sv, r1 * 4 + cc2);
                    float g = __shfl_sync(0xffffu, sv, r2 * 4 + cc0);
                    float h = __shfl_sync(0xffffu, sv, r2 * 4 + cc1);
                    float i2 = __shfl_sync(0xffffu, sv, r2 * 4 + cc2);
                    float minor = a * (e * i2 - f * h) - b * (d * i2 - f * g) + c * (d * h - e * g);
                    float cof = ((m + n) & 1) ? -minor : minor;
                    float dv = sv * cof;
                    dv += __shfl_xor_sync(0xffffu, dv, 1);
                    dv += __shfl_xor_sync(0xffffu, dv, 2);
                    float cofT = __shfl_sync(0xffffu, cof, n * 4 + m);
                    float rdet = __fdividef(1.f, dv);
                    rdet = __shfl_sync(0xffffu, rdet, 0);
                    sSi[m][n] = cofT * rdet;   // Sinv = adj(S)/det
                }
            } else {
                // --- warps 1-7: FP[i][j] (register) ---
                {
                    float a0 = 0.f, a1 = 0.f, a2 = 0.f, a3 = 0.f;
#pragma unroll
                    for (int k = 0; k < 16; k += 4) {
                        a0 = fmaf(sF[i][k + 0], cur[k + 0][j], a0);
                        a1 = fmaf(sF[i][k + 1], cur[k + 1][j], a1);
                        a2 = fmaf(sF[i][k + 2], cur[k + 2][j], a2);
                        a3 = fmaf(sF[i][k + 3], cur[k + 3][j], a3);
                    }
                    fpreg = (a0 + a1) + (a2 + a3);
                }
                // warps 6-7: FP rows 0 / 1 for warp0 (split-dot, 2 lanes/col)
                if (wp >= 6) {
                    int row = wp - 6;
                    int jd = l >> 1, kh = (l & 1) << 3;
                    float b0 = 0.f, b1 = 0.f;
#pragma unroll
                    for (int k = 0; k < 8; k += 2) {
                        b0 = fmaf(sF[row][kh + k + 0], cur[kh + k + 0][jd], b0);
                        b1 = fmaf(sF[row][kh + k + 1], cur[kh + k + 1][jd], b1);
                    }
                    float bb = b0 + b1;
                    bb += __shfl_xor_sync(0xffffffffu, bb, 1);
                    if ((l & 1) == 0) sFP01[row][jd] = bb;
                }
                asm volatile("bar.sync 1, 256;" ::: "memory");
                // warps 2-3: FHP[i][n] = sum_k F[i][k] * HP[n][k]
                if (tid >= 64 && tid < 128) {
                    int ii = (tid - 64) >> 2, n = (tid - 64) & 3;
                    float a0 = 0.f, a1 = 0.f, a2 = 0.f, a3 = 0.f;
#pragma unroll
                    for (int k = 0; k < 16; k += 4) {
                        a0 = fmaf(sF[ii][k + 0], sHP[n][k + 0], a0);
                        a1 = fmaf(sF[ii][k + 1], sHP[n][k + 1], a1);
                        a2 = fmaf(sF[ii][k + 2], sHP[n][k + 2], a2);
                        a3 = fmaf(sF[ii][k + 3], sHP[n][k + 3], a3);
                    }
                    sFHP[ii][n] = (a0 + a1) + (a2 + a3);
                }
            }
            __syncthreads();   // bar2: Si, FHP, FP01 ready

            // stage3': ALL threads redundantly compute L-row i, then
            //   A[i][j] = F - Lrow.Hcol_j ; treg = FP - Lrow.HPcol_j.
            //   tid 64..127: L -> smem/blob. tid 128..191: LR = FHP*(Si*R).
            float areg, treg;
            {
                float L0, L1, L2, L3;
                {
                    float f0 = sFHP[i][0], f1 = sFHP[i][1], f2 = sFHP[i][2], f3 = sFHP[i][3];
                    L0 = f0 * sSi[0][0];
                    L1 = f0 * sSi[0][1];
                    L2 = f0 * sSi[0][2];
                    L3 = f0 * sSi[0][3];
                    L0 = fmaf(f1, sSi[1][0], L0);
                    L1 = fmaf(f1, sSi[1][1], L1);
                    L2 = fmaf(f1, sSi[1][2], L2);
                    L3 = fmaf(f1, sSi[1][3], L3);
                    L0 = fmaf(f2, sSi[2][0], L0);
                    L1 = fmaf(f2, sSi[2][1], L1);
                    L2 = fmaf(f2, sSi[2][2], L2);
                    L3 = fmaf(f2, sSi[2][3], L3);
                    L0 = fmaf(f3, sSi[3][0], L0);
                    L1 = fmaf(f3, sSi[3][1], L1);
                    L2 = fmaf(f3, sSi[3][2], L2);
                    L3 = fmaf(f3, sSi[3][3], L3);
                }
                float a = sF[i][j];
                a = fmaf(-L0, sH[0][j], a);
                a = fmaf(-L1, sH[1][j], a);
                a = fmaf(-L2, sH[2][j], a);
                a = fmaf(-L3, sH[3][j], a);
                areg = a;
                sA[i][j] = a;
                base[(c4 * 20 + i) * 4 + w] = a;
                float fp = (wp == 0) ? sFP01[i][j] : fpreg;
                float tt = fp;
                tt = fmaf(-L0, sHP[0][j], tt);
                tt = fmaf(-L1, sHP[1][j], tt);
                tt = fmaf(-L2, sHP[2][j], tt);
                tt = fmaf(-L3, sHP[3][j], tt);
                treg = tt;
            }
            if (tid >= 64 && tid < 128) {
                int ii = (tid - 64) >> 2, m = (tid - 64) & 3;
                float acc = 0.f;
#pragma unroll
                for (int n = 0; n < 4; n++) acc = fmaf(sFHP[ii][n], sSi[n][m], acc);
                sL[ii][m] = acc;
                base[(4 * 20 + ii) * 4 + m] = acc;
            } else if (tid >= 128 && tid < 192) {
                int ii = (tid - 128) >> 2, m = (tid - 128) & 3;
                float sir0 = 0.f, sir1 = 0.f, sir2 = 0.f, sir3 = 0.f;
#pragma unroll
                for (int n = 0; n < 4; n++) {
                    float rn = sR[n][m];
                    sir0 = fmaf(sSi[0][n], rn, sir0);
                    sir1 = fmaf(sSi[1][n], rn, sir1);
                    sir2 = fmaf(sSi[2][n], rn, sir2);
                    sir3 = fmaf(sSi[3][n], rn, sir3);
                }
                float acc = sFHP[ii][0] * sir0;
                acc = fmaf(sFHP[ii][1], sir1, acc);
                acc = fmaf(sFHP[ii][2], sir2, acc);
                acc = fmaf(sFHP[ii][3], sir3, acc);
                sLR[ii][m] = acc;
            }
            __syncthreads();   // bar3

            // stage4': P' = T A^T + LR L^T + Q (T row via shfl of treg);
            //          HA on warps 6-7, HB on tid 176..191.
            if (tid >= 192) {
                int m = (tid - 192) >> 4, jj = tid & 15;
                float acc = 0.f;
#pragma unroll
                for (int k = 0; k < 16; k++) acc = fmaf(sH[m][k], sA[k][jj], acc);
                sHA[m][jj] = acc;
                base[((jj >> 2) * 20 + 16 + m) * 4 + (jj & 3)] = acc;
            } else if (tid >= 176) {
                int m = (tid - 176) >> 2, n = (tid - 176) & 3;
                float acc = 0.f;
#pragma unroll
                for (int k = 0; k < 16; k++) acc = fmaf(sH[m][k], sL[k][n], acc);
                sHB[m][n] = acc;
                base[(4 * 20 + 16 + m) * 4 + n] = acc;
            }
            int flag;
            {
                float a0 = sQ[i][j], a1 = 0.f, a2 = 0.f, a3 = 0.f;
#pragma unroll
                for (int k = 0; k < 16; k += 4) {
                    a0 = fmaf(__shfl_sync(0xffffffffu, treg, half | (k + 0)), sA[j][k + 0], a0);
                    a1 = fmaf(__shfl_sync(0xffffffffu, treg, half | (k + 1)), sA[j][k + 1], a1);
                    a2 = fmaf(__shfl_sync(0xffffffffu, treg, half | (k + 2)), sA[j][k + 2], a2);
                    a3 = fmaf(__shfl_sync(0xffffffffu, treg, half | (k + 3)), sA[j][k + 3], a3);
                }
                float acc = (a0 + a1) + (a2 + a3);
#pragma unroll
                for (int m = 0; m < 4; m++) acc = fmaf(sLR[i][m], sL[j][m], acc);
                float oldp = cur[i][j];
                // NaN-safe (NaN -> flag=1)
                flag = !(fabsf(acc - oldp) <= 2e-3f * fabsf(acc) + 2e-4f);
                nxt[i][j] = acc;
            }
            if (!__syncthreads_or(flag)) {   // bar4 (loop barrier)
                // converged: publish constant-tail marker FIRST (fast path
                // never reads the replicated blob), then replicate as the
                // stale-read fallback, then release g_ready.
                if (tid == 0) {
                    __threadfence();
                    *(volatile int*)&g_conv_chunk = (t + CH) / CH;  // ceil((t+1)/CH)
                }
                for (int t2 = t + 1; t2 < NSTEP; ++t2) {
                    float* b2 = blob + t2 * 400;
                    b2[(c4 * 20 + i) * 4 + w] = sA[i][j];
                    if (j < 4) b2[(4 * 20 + i) * 4 + j] = sL[i][j];
                    if (i < 4) b2[(c4 * 20 + 16 + i) * 4 + w] = sHA[i][j];
                    if (i < 4 && j < 4) b2[(4 * 20 + 16 + i) * 4 + j] = sHB[i][j];
                }
                __syncthreads();
                if (tid == 0) {
                    __threadfence();
                    *(volatile int*)&g_ready = NCHUNK;
                }
                return;
            }
            if (((t + 1) % CH) == 0) {
                if (tid == 0) {
                    __threadfence();
                    *(volatile int*)&g_ready = (t + 1) / CH;
                }
            }
        }
        return;
    }

    // ==================== CONSUMERS: warp-per-batch scan =====================
    const int lane = tid & 31;
    const int wrp = tid >> 5;
    const int b = ((blockIdx.x - 1) << 3) + wrp;
    const int g = (lane < 20) ? lane : 0;

    // wait for chunk 0 (also guarantees g_s0/g_y0 visible)
    if (tid == 0) {
        while (*(volatile int*)&g_ready < 1) __nanosleep(100);
        __threadfence();
    }
    __syncthreads();

    float x = (lane < 16) ? g_s0[lane] : 0.f;
    float* op = out + b * (NT * NM);
    const float* ip = inp + b * (NT * NM);
    if (lane >= 16 && lane < 20) op[lane - 16] = g_y0[lane - 16];

    const float4* gb = g_blob;
    const int bb = (blockIdx.x - 1) << 3;

    float4 A[5];     // persists across chunks: holds last step's map
    int t = 0;

#pragma unroll 1
    for (int c = 0; c < NCHUNK; ++c) {
        if (c > 0) {
            // block-uniform decision: stage chunk c, or switch to the
            // constant-map fast path (maps fixed from chunk g_conv_chunk on).
            if (tid == 0) {
                int go = 0;
                for (;;) {
                    if (*(volatile int*)&g_conv_chunk <= c) { go = 1; break; }
                    if (*(volatile int*)&g_ready >= c + 1) break;
                    __nanosleep(100);
                }
                __threadfence();
                sgo = go;
            }
            __syncthreads();
            if (sgo) break;   // uniform exit -> fast path; A = fixed map
        }
        // stage chunk c blob + this block's obs into shared
#pragma unroll
        for (int r = 0; r < 6; r++) {
            int idx = tid + r * 256;
            if (idx < CHF4) sbuf[idx] = gb[c * CHF4 + idx];
        }
        if (tid < 8 * CH) {
            int w2 = tid / CH, s = tid - w2 * CH;
            int tt = c * CH + s;   // <= 254
            sobs[w2][s] = *(const float4*)(inp + ((bb + w2) * NT + tt) * 4);
        }
        __syncthreads();

        const float4* s4 = sbuf;
#pragma unroll 1
        for (int s = 0; s < CH; ++s, ++t) {
#pragma unroll
            for (int cc = 0; cc < 5; cc++) A[cc] = s4[s * 100 + cc * 20 + g];
            float4 ob = sobs[wrp][s];
            KF_STEP(A, ob, t);
        }
        __syncthreads();  // all readers done before next chunk overwrites
    }

    // ---- constant-map fast path: barrier-free, obs prefetched 3 deep ----
    if (t < NSTEP) {
        float4 o0 = *(const float4*)(ip + t * 4);
        float4 o1 = (t + 1 < NSTEP) ? *(const float4*)(ip + (t + 1) * 4) : o0;
        float4 o2 = (t + 2 < NSTEP) ? *(const float4*)(ip + (t + 2) * 4) : o0;
#pragma unroll 3
        for (; t < NSTEP; ++t) {
            int tn = (t + 3 < NSTEP) ? t + 3 : t;
            float4 on = *(const float4*)(ip + tn * 4);
            KF_STEP(A, o0, t);
            o0 = o1; o1 = o2; o2 = on;
        }
    }
}

extern "C" void kernel_launch(void* const* d_in, const int* in_sizes, int n_in,
                              void* d_out, int out_size) {
    const float* inp = (const float*)d_in[0];
    const float* F   = (const float*)d_in[1];
    const float* H   = (const float*)d_in[2];
    const float* Q   = (const float*)d_in[3];
    const float* R   = (const float*)d_in[4];
    const float* x0  = (const float*)d_in[5];
    const float* sd  = (const float*)d_in[6];
    float* out = (float*)d_out;

    reset_kernel<<<1, 1>>>();
    fused_kernel<<<129, 256>>>(inp, out, F, H, Q, R, x0, sd);
}